// round 4
// baseline (speedup 1.0000x reference)
#include <cuda_runtime.h>
#include <cstdint>
#include <math_constants.h>

#define CD    256
#define NPIX  65536
#define NCODE 1024
#define PATCH 48

// ---------------- device scratch (no allocs allowed) ----------------
__device__ float g_Wcomb[PATCH*CD];     // [p][c] combined encoder+conv1 weight
__device__ float g_bcomb[CD];
__device__ float g_cnorm[NCODE];        // C = ||c||^2  (full, not half)
__device__ float g_cb2[NCODE*CD];       // codebook @ W2^T + b2
__device__ float g_cb3[NCODE*PATCH];    // cb2 @ dec_w (spatially flipped)
__device__ float g_z[NPIX*CD];          // 64 MB
__device__ float g_znorm[NPIX];         // A = ||z||^2
__device__ float g_dmin[NPIX];
__device__ int   g_idx[NPIX];
__device__ float g_idxf_dummy[NPIX];
__device__ float g_part[256];

// ---------------- f32x2 helpers (Blackwell packed fp32) ----------------
// Per-lane rounding of fma.rn.f32x2 == scalar __fmaf_rn: each lane is an
// independent sequential ascending-k fused-FMA chain (matches Eigen gebp).
__device__ __forceinline__ uint64_t pack2(float a) {
    uint64_t r; uint32_t ai = __float_as_uint(a);
    asm("mov.b64 %0, {%1, %1};" : "=l"(r) : "r"(ai));
    return r;
}
__device__ __forceinline__ void ffma2(uint64_t& c, uint64_t a, uint64_t b) {
    asm("fma.rn.f32x2 %0, %1, %2, %3;" : "=l"(c) : "l"(a), "l"(b), "l"(c));
}
__device__ __forceinline__ void unpack2(uint64_t v, float& lo, float& hi) {
    uint32_t l, h;
    asm("mov.b64 {%0, %1}, %2;" : "=r"(l), "=r"(h) : "l"(v));
    lo = __uint_as_float(l); hi = __uint_as_float(h);
}

// ---------------- precompute: Wcomb[p][c] = sum_o We[o][p]*W1[c][o]; bcomb ----------------
__global__ void k_comb(const float* __restrict__ enc_w, const float* __restrict__ enc_b,
                       const float* __restrict__ w1, const float* __restrict__ b1)
{
    int c = threadIdx.x;
    int p = blockIdx.x;
    if (p < PATCH) {
        float s = 0.f;
        for (int o = 0; o < CD; ++o) s += enc_w[o*PATCH + p] * w1[c*CD + o];
        g_Wcomb[p*CD + c] = s;
    } else {
        float s = b1[c];
        for (int o = 0; o < CD; ++o) s += enc_b[o] * w1[c*CD + o];
        g_bcomb[c] = s;
    }
}

// C_k = ||c_k||^2 (order-insensitive at 1e-11 << grid; float4 ok)
__global__ void k_cnorm(const float* __restrict__ cb) {
    int k = blockIdx.x * blockDim.x + threadIdx.x;
    const float* r = cb + k*CD;
    float s = 0.f;
    for (int j = 0; j < CD; j += 4) {
        float4 v = *(const float4*)(r + j);
        s += v.x*v.x + v.y*v.y + v.z*v.z + v.w*v.w;
    }
    g_cnorm[k] = s;
}

// cb2[k][c] = sum_j codebook[k][j]*W2[c][j] + b2[c]  -- tiled NT GEMM 1024x256x256
__global__ void k_cb2(const float* __restrict__ A, const float* __restrict__ B,
                      const float* __restrict__ bias)
{
    __shared__ float As[64][17];
    __shared__ float Bs[16][65];
    int tx = threadIdx.x & 15, ty = threadIdx.x >> 4;
    int m0 = blockIdx.x * 64, n0 = blockIdx.y * 64;
    float acc[4][4] = {};
    for (int kt = 0; kt < 256; kt += 16) {
        {
            int f = threadIdx.x;
            int row = f >> 2, q = f & 3;
            float4 v = *(const float4*)&A[(m0+row)*256 + kt + q*4];
            As[row][q*4+0]=v.x; As[row][q*4+1]=v.y; As[row][q*4+2]=v.z; As[row][q*4+3]=v.w;
            float4 w = *(const float4*)&B[(n0+row)*256 + kt + q*4];
            Bs[q*4+0][row]=w.x; Bs[q*4+1][row]=w.y; Bs[q*4+2][row]=w.z; Bs[q*4+3][row]=w.w;
        }
        __syncthreads();
        #pragma unroll
        for (int kk = 0; kk < 16; ++kk) {
            float a[4], b[4];
            #pragma unroll
            for (int i = 0; i < 4; ++i) a[i] = As[ty*4+i][kk];
            #pragma unroll
            for (int j = 0; j < 4; ++j) b[j] = Bs[kk][tx*4+j];
            #pragma unroll
            for (int i = 0; i < 4; ++i)
                #pragma unroll
                for (int j = 0; j < 4; ++j) acc[i][j] += a[i]*b[j];
        }
        __syncthreads();
    }
    #pragma unroll
    for (int i = 0; i < 4; ++i)
        #pragma unroll
        for (int j = 0; j < 4; ++j)
            g_cb2[(m0+ty*4+i)*256 + n0+tx*4+j] = acc[i][j] + bias[n0+tx*4+j];
}

// cb3[k][q] with flip: conv_transpose(VALID, k=s=4, no kernel transpose) -> w[3-ki][3-kj]
__global__ void k_cb3(const float* __restrict__ dec_w) {
    __shared__ float row[CD];
    int k = blockIdx.x;
    for (int c = threadIdx.x; c < CD; c += 64) row[c] = g_cb2[k*CD + c];
    __syncthreads();
    int q = threadIdx.x;
    if (q < PATCH) {
        int o = q >> 4, r = q & 15, ki = r >> 2, kj = r & 3;
        int qf = o*16 + (3-ki)*4 + (3-kj);
        float s = 0.f;
        for (int c = 0; c < CD; ++c) s += row[c] * dec_w[c*PATCH + qf];
        g_cb3[k*PATCH + q] = s;
    }
}

// ---------------- z = patches @ Wcomb + bcomb : 65536 x 256, K=48 ----------------
__global__ void k_z(const float* __restrict__ x) {
    __shared__ float Ps[64][49];
    __shared__ float Ws[48][65];
    int tx = threadIdx.x & 15, ty = threadIdx.x >> 4;
    int m0 = blockIdx.x * 64, n0 = blockIdx.y * 64;
    for (int e = threadIdx.x; e < 64*48; e += 256) {
        int pix = e / 48, p = e - pix*48;
        int n = m0 + pix;
        int b = n >> 12, rem = n & 4095, i = rem >> 6, j = rem & 63;
        int cin = p >> 4, r = p & 15, ki = r >> 2, kj = r & 3;
        Ps[pix][p] = x[(((b*3 + cin) << 8) + (i*4 + ki))*256 + j*4 + kj];
    }
    for (int e = threadIdx.x; e < 48*16; e += 256) {
        int row = e >> 4, q = e & 15;
        float4 v = *(const float4*)&g_Wcomb[row*CD + n0 + q*4];
        Ws[row][q*4+0]=v.x; Ws[row][q*4+1]=v.y; Ws[row][q*4+2]=v.z; Ws[row][q*4+3]=v.w;
    }
    __syncthreads();
    float acc[4][4] = {};
    #pragma unroll 8
    for (int k = 0; k < 48; ++k) {
        float a[4], b[4];
        #pragma unroll
        for (int i = 0; i < 4; ++i) a[i] = Ps[ty*4+i][k];
        #pragma unroll
        for (int j = 0; j < 4; ++j) b[j] = Ws[k][tx*4+j];
        #pragma unroll
        for (int i = 0; i < 4; ++i)
            #pragma unroll
            for (int j = 0; j < 4; ++j) acc[i][j] += a[i]*b[j];
    }
    #pragma unroll
    for (int i = 0; i < 4; ++i)
        #pragma unroll
        for (int j = 0; j < 4; ++j)
            g_z[(m0+ty*4+i)*CD + n0+tx*4+j] = acc[i][j] + g_bcomb[n0+tx*4+j];
}

__global__ void k_znorm() {
    int row  = (blockIdx.x << 3) + (threadIdx.x >> 5);
    int lane = threadIdx.x & 31;
    const float* r = g_z + (size_t)row * CD;
    float4 a = *(const float4*)(r + lane*4);
    float4 b = *(const float4*)(r + 128 + lane*4);
    float s = a.x*a.x + a.y*a.y + a.z*a.z + a.w*a.w
            + b.x*b.x + b.y*b.y + b.z*b.z + b.w*b.w;
    #pragma unroll
    for (int off = 16; off; off >>= 1) s += __shfl_down_sync(0xffffffffu, s, off);
    if (!lane) g_znorm[row] = s;
}

// ---------------- distance GEMM + fused argmin (dominant kernel) ----------------
// M = z_n . c_k via sequential ascending-k fused-FMA chain (per f32x2 lane).
// Then REPLICATE the reference's quantized distance EXACTLY:
//     d = fl( fl( A - fl(2*M) ) + C )      (all fp32, round-to-nearest)
// and argmin with first-index tie-break. The 3e-5 quantization grid of d is
// what decides ~0.6% of rows; comparing unquantized scores caused the 78 flips.
__global__ void __launch_bounds__(256, 2) k_dist(const float* __restrict__ codebook,
                                                 float* __restrict__ idx_out)
{
    __shared__ __align__(16) float Zs[128][17];
    __shared__ __align__(16) float Cs[16][132];
    int m0 = blockIdx.x * 128;
    int tx = threadIdx.x & 15, ty = threadIdx.x >> 4;

    float Arow[8];
    #pragma unroll
    for (int ii = 0; ii < 8; ++ii) {
        int row = 32*(ii >> 1) + 2*ty + (ii & 1);
        Arow[ii] = g_znorm[m0 + row];
    }

    float best[8]; int bidx[8];
    #pragma unroll
    for (int i = 0; i < 8; ++i) { best[i] = CUDART_INF_F; bidx[i] = NCODE; }

    for (int nt = 0; nt < 8; ++nt) {
        uint64_t acc[8][4];
        #pragma unroll
        for (int i = 0; i < 8; ++i)
            #pragma unroll
            for (int j = 0; j < 4; ++j) acc[i][j] = 0ull;

        for (int kt = 0; kt < 256; kt += 16) {
            #pragma unroll
            for (int f = threadIdx.x; f < 512; f += 256) {
                int row = f >> 2, q = f & 3;
                float4 v = *(const float4*)&g_z[(m0+row)*256 + kt + q*4];
                Zs[row][q*4+0]=v.x; Zs[row][q*4+1]=v.y; Zs[row][q*4+2]=v.z; Zs[row][q*4+3]=v.w;
            }
            #pragma unroll
            for (int f = threadIdx.x; f < 512; f += 256) {
                int code = f >> 2, q = f & 3;
                float4 v = *(const float4*)&codebook[(nt*128+code)*256 + kt + q*4];
                Cs[q*4+0][code]=v.x; Cs[q*4+1][code]=v.y; Cs[q*4+2][code]=v.z; Cs[q*4+3][code]=v.w;
            }
            __syncthreads();
            #pragma unroll
            for (int kk = 0; kk < 16; ++kk) {
                uint64_t bv[4];
                #pragma unroll
                for (int jj = 0; jj < 4; ++jj)
                    bv[jj] = *reinterpret_cast<const uint64_t*>(&Cs[kk][32*jj + 2*tx]);
                #pragma unroll
                for (int ii = 0; ii < 8; ++ii) {
                    int row = 32*(ii >> 1) + 2*ty + (ii & 1);
                    uint64_t av = pack2(Zs[row][kk]);
                    #pragma unroll
                    for (int jj = 0; jj < 4; ++jj) ffma2(acc[ii][jj], av, bv[jj]);
                }
            }
            __syncthreads();
        }
        // epilogue: reference-exact d, running argmin (codes ascend per thread
        // across nt/jj => strict < keeps first index)
        #pragma unroll
        for (int jj = 0; jj < 4; ++jj) {
            int code = nt*128 + 32*jj + 2*tx;
            float C0 = g_cnorm[code], C1 = g_cnorm[code+1];
            #pragma unroll
            for (int ii = 0; ii < 8; ++ii) {
                float s0, s1; unpack2(acc[ii][jj], s0, s1);
                float t0 = __fadd_rn(Arow[ii], -__fadd_rn(s0, s0)); // A - 2M, rn
                float t1 = __fadd_rn(Arow[ii], -__fadd_rn(s1, s1));
                float d0 = __fadd_rn(t0, C0);
                float d1 = __fadd_rn(t1, C1);
                if (d0 < best[ii]) { best[ii] = d0; bidx[ii] = code; }
                if (d1 < best[ii]) { best[ii] = d1; bidx[ii] = code + 1; }
            }
        }
    }

    // cross-thread (tx) reduction via smem reuse; first-index on exact ties
    __syncthreads();
    float* redS = &Zs[0][0];
    int*   redI = (int*)&Cs[0][0];
    #pragma unroll
    for (int ii = 0; ii < 8; ++ii) {
        int row = 32*(ii >> 1) + 2*ty + (ii & 1);
        redS[row*16 + tx] = best[ii];
        redI[row*16 + tx] = bidx[ii];
    }
    __syncthreads();
    if (threadIdx.x < 128) {
        int row = threadIdx.x;
        float bs = redS[row*16]; int bi = redI[row*16];
        #pragma unroll
        for (int t = 1; t < 16; ++t) {
            float s = redS[row*16 + t]; int i2 = redI[row*16 + t];
            if (s < bs || (s == bs && i2 < bi)) { bs = s; bi = i2; }
        }
        int n = m0 + row;
        g_idx[n]  = bi;
        g_dmin[n] = bs;
        float* op = idx_out ? idx_out : g_idxf_dummy;
        op[n] = (float)bi;
    }
}

// ---------------- decode: scatter cb3[idx] into 4x4 output blocks ----------------
__global__ void k_decode(const float* __restrict__ dec_b, float* __restrict__ out) {
    int t = blockIdx.x * 256 + threadIdx.x;     // float4 index
    int v = t << 2;
    int j  = (v >> 2) & 63;
    int y  = (v >> 8) & 255;
    int bo = v >> 16;                            // b*3 + o
    int b  = bo / 3;
    int o  = bo - b*3;
    int i  = y >> 2, ki = y & 3;
    int n  = (b << 12) + (i << 6) + j;
    int id = g_idx[n];
    float4 w = *(const float4*)&g_cb3[id*PATCH + o*16 + (ki << 2)];
    float bb = dec_b[o];
    float4 r = make_float4(w.x + bb, w.y + bb, w.z + bb, w.w + bb);
    ((float4*)out)[t] = r;
}

// ---------------- deterministic loss reduction ----------------
__global__ void k_loss1() {
    __shared__ float sm[256];
    int t = threadIdx.x;
    sm[t] = g_dmin[blockIdx.x*256 + t];
    __syncthreads();
    for (int s = 128; s > 0; s >>= 1) { if (t < s) sm[t] += sm[t+s]; __syncthreads(); }
    if (!t) g_part[blockIdx.x] = sm[0];
}
__global__ void k_loss2(float* __restrict__ loss_out) {
    __shared__ float sm[256];
    int t = threadIdx.x;
    sm[t] = g_part[t];
    __syncthreads();
    for (int s = 128; s > 0; s >>= 1) { if (t < s) sm[t] += sm[t+s]; __syncthreads(); }
    if (!t) *loss_out = 1.25f * sm[0] / 16777216.0f;
}

// ---------------- launch ----------------
extern "C" void kernel_launch(void* const* d_in, const int* in_sizes, int n_in,
                              void* d_out, int out_size)
{
    const float* x     = (const float*)d_in[0];
    const float* enc_w = (const float*)d_in[1];
    const float* enc_b = (const float*)d_in[2];
    const float* w1    = (const float*)d_in[3];
    const float* b1    = (const float*)d_in[4];
    const float* cb    = (const float*)d_in[5];
    const float* w2    = (const float*)d_in[6];
    const float* b2    = (const float*)d_in[7];
    const float* dw    = (const float*)d_in[8];
    const float* db    = (const float*)d_in[9];
    float* out = (float*)d_out;

    k_comb <<<49, 256>>>(enc_w, enc_b, w1, b1);
    k_cnorm<<<4, 256>>>(cb);
    k_cb2  <<<dim3(16,4), 256>>>(cb, w2, b2);
    k_cb3  <<<1024, 64>>>(dw);
    k_z    <<<dim3(1024,4), 256>>>(x);
    k_znorm<<<8192, 256>>>();

    bool has_idx  = out_size >= 3145728 + 65536;
    bool has_loss = out_size >= 3145728 + 65536 + 1;
    k_dist <<<512, 256>>>(cb, has_idx ? out + 3145728 : nullptr);
    k_decode<<<3072, 256>>>(db, out);
    if (has_loss) {
        k_loss1<<<256, 256>>>();
        k_loss2<<<1, 256>>>(out + 3145728 + 65536);
    }
}

// round 6
// speedup vs baseline: 1.9356x; 1.9356x over previous
#include <cuda_runtime.h>
#include <cuda_bf16.h>
#include <cstdint>
#include <math_constants.h>

#define CD    256
#define NPIX  65536
#define NCODE 1024
#define PATCH 48
#define CAND_CAP (1<<22)
#define TAU 4e-3f

__device__ float g_Wcomb[PATCH*CD];
__device__ float g_bcomb[CD];
__device__ float g_cnorm[NCODE];
__device__ float g_cb2[NCODE*CD];
__device__ float g_cb3[NCODE*PATCH];
__device__ float g_z[NPIX*CD];
__device__ __nv_bfloat16 g_zh[NPIX*CD];
__device__ __nv_bfloat16 g_cbh[NCODE*CD];
__device__ float g_znorm[NPIX];
__device__ float g_dmin[NPIX];
__device__ int   g_idx[NPIX];
__device__ float g_idxf_dummy[NPIX];
__device__ float g_part[256];
__device__ unsigned long long g_key[NPIX];
__device__ unsigned int g_cand[CAND_CAP];
__device__ int g_ncand;

__device__ __forceinline__ uint32_t bf2pack(float lo, float hi){
    uint32_t r; asm("cvt.rn.bf16x2.f32 %0, %1, %2;" : "=r"(r) : "f"(hi), "f"(lo)); return r;
}
__device__ __forceinline__ unsigned encf(float f){
    unsigned b = __float_as_uint(f);
    return (b & 0x80000000u) ? ~b : (b | 0x80000000u);
}
__device__ __forceinline__ float decf(unsigned u){
    return __uint_as_float((u & 0x80000000u) ? (u ^ 0x80000000u) : ~u);
}

__global__ void k_comb(const float* __restrict__ enc_w, const float* __restrict__ enc_b,
                       const float* __restrict__ w1, const float* __restrict__ b1){
    int c = threadIdx.x, p = blockIdx.x;
    if (p < PATCH) {
        float s = 0.f;
        for (int o = 0; o < CD; ++o) s += enc_w[o*PATCH+p] * w1[c*CD+o];
        g_Wcomb[p*CD+c] = s;
    } else {
        float s = b1[c];
        for (int o = 0; o < CD; ++o) s += enc_b[o] * w1[c*CD+o];
        g_bcomb[c] = s;
    }
}

__global__ void k_cnorm(const float* __restrict__ cb){
    int k = blockIdx.x*256 + threadIdx.x;
    const float* r = cb + k*CD; float s = 0.f;
    for (int j = 0; j < CD; j += 4) {
        float4 v = *(const float4*)(r+j);
        s += v.x*v.x + v.y*v.y + v.z*v.z + v.w*v.w;
    }
    g_cnorm[k] = s;
}

__global__ void k_cbh(const float* __restrict__ cb){
    int i = blockIdx.x*256 + threadIdx.x;
    g_cbh[i] = __float2bfloat16(cb[i]);
}

__global__ void k_cb2(const float* __restrict__ A, const float* __restrict__ B,
                      const float* __restrict__ bias){
    __shared__ float As[64][17]; __shared__ float Bs[16][65];
    int tx = threadIdx.x & 15, ty = threadIdx.x >> 4;
    int m0 = blockIdx.x*64, n0 = blockIdx.y*64;
    float acc[4][4] = {};
    for (int kt = 0; kt < 256; kt += 16) {
        int f = threadIdx.x, row = f>>2, q = f&3;
        float4 v = *(const float4*)&A[(m0+row)*256 + kt + q*4];
        As[row][q*4]=v.x; As[row][q*4+1]=v.y; As[row][q*4+2]=v.z; As[row][q*4+3]=v.w;
        float4 w = *(const float4*)&B[(n0+row)*256 + kt + q*4];
        Bs[q*4][row]=w.x; Bs[q*4+1][row]=w.y; Bs[q*4+2][row]=w.z; Bs[q*4+3][row]=w.w;
        __syncthreads();
        #pragma unroll
        for (int kk = 0; kk < 16; ++kk) {
            float a[4], b[4];
            #pragma unroll
            for (int i = 0; i < 4; ++i) a[i] = As[ty*4+i][kk];
            #pragma unroll
            for (int j = 0; j < 4; ++j) b[j] = Bs[kk][tx*4+j];
            #pragma unroll
            for (int i = 0; i < 4; ++i)
                #pragma unroll
                for (int j = 0; j < 4; ++j) acc[i][j] += a[i]*b[j];
        }
        __syncthreads();
    }
    #pragma unroll
    for (int i = 0; i < 4; ++i)
        #pragma unroll
        for (int j = 0; j < 4; ++j)
            g_cb2[(m0+ty*4+i)*256 + n0+tx*4+j] = acc[i][j] + bias[n0+tx*4+j];
}

__global__ void k_cb3(const float* __restrict__ dec_w){
    __shared__ float row[CD];
    int k = blockIdx.x;
    for (int c = threadIdx.x; c < CD; c += 64) row[c] = g_cb2[k*CD+c];
    __syncthreads();
    int q = threadIdx.x;
    if (q < PATCH) {
        int o = q>>4, r = q&15, ki = r>>2, kj = r&3;
        int qf = o*16 + (3-ki)*4 + (3-kj);
        float s = 0.f;
        for (int c = 0; c < CD; ++c) s += row[c] * dec_w[c*PATCH+qf];
        g_cb3[k*PATCH+q] = s;
    }
}

__global__ void k_z(const float* __restrict__ x){
    __shared__ float Ps[64][49]; __shared__ float Ws[48][65];
    int tx = threadIdx.x & 15, ty = threadIdx.x >> 4;
    int m0 = blockIdx.x*64, n0 = blockIdx.y*64;
    for (int e = threadIdx.x; e < 768; e += 256) {
        int pix = e/12, r = e - pix*12;
        int n = m0+pix, b = n>>12, rem = n&4095, i = rem>>6, j = rem&63;
        int cin = r>>2, ki = r&3;
        float4 v = *(const float4*)&x[(((b*3+cin)<<8) + (i*4+ki))*256 + j*4];
        Ps[pix][r*4]=v.x; Ps[pix][r*4+1]=v.y; Ps[pix][r*4+2]=v.z; Ps[pix][r*4+3]=v.w;
    }
    for (int e = threadIdx.x; e < 768; e += 256) {
        int row = e>>4, q = e&15;
        float4 v = *(const float4*)&g_Wcomb[row*CD + n0 + q*4];
        Ws[row][q*4]=v.x; Ws[row][q*4+1]=v.y; Ws[row][q*4+2]=v.z; Ws[row][q*4+3]=v.w;
    }
    __syncthreads();
    float acc[4][4] = {};
    #pragma unroll 8
    for (int k = 0; k < 48; ++k) {
        float a[4], b[4];
        #pragma unroll
        for (int i = 0; i < 4; ++i) a[i] = Ps[ty*4+i][k];
        #pragma unroll
        for (int j = 0; j < 4; ++j) b[j] = Ws[k][tx*4+j];
        #pragma unroll
        for (int i = 0; i < 4; ++i)
            #pragma unroll
            for (int j = 0; j < 4; ++j) acc[i][j] += a[i]*b[j];
    }
    float b0 = g_bcomb[n0+tx*4], b1 = g_bcomb[n0+tx*4+1];
    float b2 = g_bcomb[n0+tx*4+2], b3 = g_bcomb[n0+tx*4+3];
    #pragma unroll
    for (int i = 0; i < 4; ++i) {
        size_t row = m0+ty*4+i;
        float4 o = make_float4(acc[i][0]+b0, acc[i][1]+b1, acc[i][2]+b2, acc[i][3]+b3);
        *(float4*)&g_z[row*CD + n0+tx*4] = o;
        *(uint2*)(g_zh + row*CD + n0+tx*4) = make_uint2(bf2pack(o.x,o.y), bf2pack(o.z,o.w));
    }
}

__global__ void k_znorm(){
    int row = (blockIdx.x<<3) + (threadIdx.x>>5), lane = threadIdx.x & 31;
    const float* r = g_z + (size_t)row*CD;
    float4 a = *(const float4*)(r + lane*4);
    float4 b = *(const float4*)(r + 128 + lane*4);
    float s = a.x*a.x+a.y*a.y+a.z*a.z+a.w*a.w + b.x*b.x+b.y*b.y+b.z*b.z+b.w*b.w;
    #pragma unroll
    for (int o = 16; o; o >>= 1) s += __shfl_down_sync(0xffffffffu, s, o);
    if (!lane) g_znorm[row] = s;
}

__global__ void k_reset(){
    int n = blockIdx.x*256 + threadIdx.x;
    g_key[n] = ~0ull;
    if (n == 0) g_ncand = 0;
}

// ---- mma.sync bf16 approx scores + smem rowmax + candidate emit ----
// CTA: 64 pixels x 1024 codes, K=256. smem: Ss scores 64x1032 bf16 (pad vs banks),
// As z 64x264 bf16, Bs codes 256x72 bf16, RM rowmax u32.
#define SS_STRIDE 1032
#define AS_STRIDE 264
#define BS_STRIDE 72
#define AS_OFF 132096
#define BS_OFF (AS_OFF + 64*AS_STRIDE*2)
#define RM_OFF (BS_OFF + 256*BS_STRIDE*2)
#define SC_SMEM (RM_OFF + 256)

__global__ void __launch_bounds__(256,1) k_score(){
    extern __shared__ char smraw[];
    __nv_bfloat16* Ss = (__nv_bfloat16*)smraw;
    __nv_bfloat16* As = (__nv_bfloat16*)(smraw + AS_OFF);
    __nv_bfloat16* Bs = (__nv_bfloat16*)(smraw + BS_OFF);
    unsigned* RM = (unsigned*)(smraw + RM_OFF);
    int tid = threadIdx.x, w = tid>>5, lane = tid&31;
    int grp = lane>>2, tig = lane&3;
    int r0 = blockIdx.x*64;
    if (tid < 64) RM[tid] = 0u;
    for (int t = tid; t < 2048; t += 256) {
        int row = t>>5, q = t&31;
        *(uint4*)(As + row*AS_STRIDE + q*8) = *((const uint4*)(g_zh + (size_t)(r0+row)*CD) + q);
    }
    unsigned lmax[8];
    #pragma unroll
    for (int i = 0; i < 8; ++i) lmax[i] = 0u;

    for (int cp = 0; cp < 4; ++cp) {
        float acc[4][4][4];
        #pragma unroll
        for (int i = 0; i < 4; ++i)
            #pragma unroll
            for (int j = 0; j < 4; ++j)
                #pragma unroll
                for (int q = 0; q < 4; ++q) acc[i][j][q] = 0.f;
        for (int kc = 0; kc < 4; ++kc) {
            __syncthreads();
            for (int t = tid; t < 2048; t += 256) {
                int row = t>>3, q = t&7;
                *(uint4*)(Bs + row*BS_STRIDE + q*8) =
                    *((const uint4*)(g_cbh + (size_t)(cp*256+row)*CD + kc*64) + q);
            }
            __syncthreads();
            #pragma unroll
            for (int k16 = 0; k16 < 4; ++k16) {
                int k0 = kc*64 + k16*16;
                uint32_t a[4][4], b[4][2];
                #pragma unroll
                for (int i = 0; i < 4; ++i) {
                    const __nv_bfloat16* ap  = As + (i*16+grp)*AS_STRIDE + k0 + tig*2;
                    const __nv_bfloat16* ap8 = As + (i*16+8+grp)*AS_STRIDE + k0 + tig*2;
                    a[i][0] = *(const uint32_t*)ap;
                    a[i][1] = *(const uint32_t*)ap8;
                    a[i][2] = *(const uint32_t*)(ap + 8);
                    a[i][3] = *(const uint32_t*)(ap8 + 8);
                }
                #pragma unroll
                for (int j = 0; j < 4; ++j) {
                    const __nv_bfloat16* bp = Bs + (w*32 + j*8 + grp)*BS_STRIDE + k16*16 + tig*2;
                    b[j][0] = *(const uint32_t*)bp;
                    b[j][1] = *(const uint32_t*)(bp + 8);
                }
                #pragma unroll
                for (int i = 0; i < 4; ++i)
                    #pragma unroll
                    for (int j = 0; j < 4; ++j)
                        asm volatile(
                            "mma.sync.aligned.m16n8k16.row.col.f32.bf16.bf16.f32 "
                            "{%0,%1,%2,%3}, {%4,%5,%6,%7}, {%8,%9}, {%0,%1,%2,%3};"
                            : "+f"(acc[i][j][0]), "+f"(acc[i][j][1]),
                              "+f"(acc[i][j][2]), "+f"(acc[i][j][3])
                            : "r"(a[i][0]), "r"(a[i][1]), "r"(a[i][2]), "r"(a[i][3]),
                              "r"(b[j][0]), "r"(b[j][1]));
            }
        }
        #pragma unroll
        for (int i = 0; i < 4; ++i)
            #pragma unroll
            for (int j = 0; j < 4; ++j) {
                int c_lo = cp*256 + w*32 + j*8 + tig*2;
                float cn0 = 0.5f*g_cnorm[c_lo], cn1 = 0.5f*g_cnorm[c_lo+1];
                float s00 = acc[i][j][0] - cn0, s01 = acc[i][j][1] - cn1;
                float s10 = acc[i][j][2] - cn0, s11 = acc[i][j][3] - cn1;
                int rlo = i*16+grp, rhi = rlo+8;
                *(uint32_t*)(Ss + rlo*SS_STRIDE + c_lo) = bf2pack(s00, s01);
                *(uint32_t*)(Ss + rhi*SS_STRIDE + c_lo) = bf2pack(s10, s11);
                unsigned e0 = encf(fmaxf(s00, s01)), e1 = encf(fmaxf(s10, s11));
                lmax[i*2]   = max(lmax[i*2],   e0);
                lmax[i*2+1] = max(lmax[i*2+1], e1);
            }
    }
    #pragma unroll
    for (int i = 0; i < 4; ++i) {
        atomicMax(&RM[i*16+grp],   lmax[i*2]);
        atomicMax(&RM[i*16+8+grp], lmax[i*2+1]);
    }
    __syncthreads();
    // threshold scan: thread t -> row t>>2, 256 cols
    int row = tid>>2, cbase = (tid&3)*256;
    float thr = decf(RM[row]) - TAU;
    const uint4* sp = (const uint4*)(Ss + row*SS_STRIDE + cbase);
    int cnt = 0;
    for (int it = 0; it < 32; ++it) {
        uint4 v = sp[it];
        uint32_t ws[4] = {v.x, v.y, v.z, v.w};
        #pragma unroll
        for (int h = 0; h < 4; ++h) {
            if (__uint_as_float(ws[h] << 16) >= thr) ++cnt;
            if (__uint_as_float(ws[h] & 0xffff0000u) >= thr) ++cnt;
        }
    }
    int incl = cnt;
    #pragma unroll
    for (int o = 1; o < 32; o <<= 1) {
        int t2 = __shfl_up_sync(0xffffffffu, incl, o);
        if (lane >= o) incl += t2;
    }
    int total = __shfl_sync(0xffffffffu, incl, 31);
    int base = 0;
    if (lane == 31 && total) base = atomicAdd(&g_ncand, total);
    base = __shfl_sync(0xffffffffu, base, 31);
    int pos = base + incl - cnt;
    if (total) {
        for (int it = 0; it < 32; ++it) {
            uint4 v = sp[it];
            uint32_t ws[4] = {v.x, v.y, v.z, v.w};
            #pragma unroll
            for (int h = 0; h < 4; ++h) {
                int c = cbase + it*8 + h*2;
                if (__uint_as_float(ws[h] << 16) >= thr) {
                    if (pos < CAND_CAP) g_cand[pos] = ((unsigned)(r0+row)<<10) | c;
                    ++pos;
                }
                if (__uint_as_float(ws[h] & 0xffff0000u) >= thr) {
                    if (pos < CAND_CAP) g_cand[pos] = ((unsigned)(r0+row)<<10) | (c+1);
                    ++pos;
                }
            }
        }
    }
}

__global__ void k_pick2(const float* __restrict__ cb){
    int total = g_ncand; if (total > CAND_CAP) total = CAND_CAP;
    for (int i = blockIdx.x*blockDim.x + threadIdx.x; i < total; i += gridDim.x*blockDim.x) {
        unsigned e = g_cand[i];
        int n = (int)(e>>10), code = (int)(e & 1023u);
        const float4* zp = (const float4*)(g_z + (size_t)n*CD);
        const float4* cp = (const float4*)(cb + (size_t)code*CD);
        float m = 0.f;
        #pragma unroll 8
        for (int q = 0; q < 64; ++q) {
            float4 a = zp[q], b = cp[q];
            m = __fmaf_rn(a.x,b.x,m); m = __fmaf_rn(a.y,b.y,m);
            m = __fmaf_rn(a.z,b.z,m); m = __fmaf_rn(a.w,b.w,m);
        }
        float t = __fadd_rn(g_znorm[n], -__fadd_rn(m,m));
        float d = __fadd_rn(t, g_cnorm[code]);
        unsigned long long key = ((unsigned long long)__float_as_uint(d)<<32) | (unsigned)code;
        atomicMin(&g_key[n], key);
    }
}

__global__ void k_pick3(float* __restrict__ idx_out){
    int n = blockIdx.x*256 + threadIdx.x;
    unsigned long long k = g_key[n];
    int bi = (int)(k & 0xffffffffu);
    g_idx[n] = bi;
    g_dmin[n] = __uint_as_float((unsigned)(k>>32));
    float* op = idx_out ? idx_out : g_idxf_dummy;
    op[n] = (float)bi;
}

__global__ void k_decode(const float* __restrict__ dec_b, float* __restrict__ out){
    int t = blockIdx.x*256 + threadIdx.x;
    int v = t<<2;
    int j = (v>>2)&63, y = (v>>8)&255, bo = v>>16;
    int b = bo/3, o = bo - b*3, i = y>>2, ki = y&3;
    int n = (b<<12) + (i<<6) + j;
    int id = g_idx[n];
    float4 w = *(const float4*)&g_cb3[id*PATCH + o*16 + (ki<<2)];
    float bb = dec_b[o];
    ((float4*)out)[t] = make_float4(w.x+bb, w.y+bb, w.z+bb, w.w+bb);
}

__global__ void k_loss1(){
    __shared__ float sm[256]; int t = threadIdx.x;
    sm[t] = g_dmin[blockIdx.x*256 + t]; __syncthreads();
    for (int s = 128; s; s >>= 1) { if (t < s) sm[t] += sm[t+s]; __syncthreads(); }
    if (!t) g_part[blockIdx.x] = sm[0];
}
__global__ void k_loss2(float* __restrict__ lo){
    __shared__ float sm[256]; int t = threadIdx.x;
    sm[t] = g_part[t]; __syncthreads();
    for (int s = 128; s; s >>= 1) { if (t < s) sm[t] += sm[t+s]; __syncthreads(); }
    if (!t) *lo = 1.25f * sm[0] / 16777216.0f;
}

extern "C" void kernel_launch(void* const* d_in, const int* in_sizes, int n_in,
                              void* d_out, int out_size){
    const float* x     = (const float*)d_in[0];
    const float* enc_w = (const float*)d_in[1];
    const float* enc_b = (const float*)d_in[2];
    const float* w1    = (const float*)d_in[3];
    const float* b1    = (const float*)d_in[4];
    const float* cb    = (const float*)d_in[5];
    const float* w2    = (const float*)d_in[6];
    const float* b2    = (const float*)d_in[7];
    const float* dw    = (const float*)d_in[8];
    const float* db    = (const float*)d_in[9];
    float* out = (float*)d_out;

    static bool attr_done = false;
    if (!attr_done) {
        cudaFuncSetAttribute(k_score, cudaFuncAttributeMaxDynamicSharedMemorySize, SC_SMEM);
        attr_done = true;
    }

    k_comb <<<49, 256>>>(enc_w, enc_b, w1, b1);
    k_cnorm<<<4, 256>>>(cb);
    k_cbh  <<<1024, 256>>>(cb);
    k_cb2  <<<dim3(16,4), 256>>>(cb, w2, b2);
    k_cb3  <<<1024, 64>>>(dw);
    k_z    <<<dim3(1024,4), 256>>>(x);
    k_znorm<<<8192, 256>>>();
    k_reset<<<256, 256>>>();
    k_score<<<1024, 256, SC_SMEM>>>();
    k_pick2<<<2048, 128>>>(cb);

    bool has_idx  = out_size >= 3145728 + 65536;
    bool has_loss = out_size >= 3145728 + 65536 + 1;
    k_pick3<<<256, 256>>>(has_idx ? out + 3145728 : nullptr);
    k_decode<<<3072, 256>>>(db, out);
    if (has_loss) {
        k_loss1<<<256, 256>>>();
        k_loss2<<<1, 256>>>(out + 3145728 + 65536);
    }
}

// round 7
// speedup vs baseline: 2.2218x; 1.1478x over previous
#include <cuda_runtime.h>
#include <cuda_bf16.h>
#include <cstdint>
#include <math_constants.h>

#define CD    256
#define NPIX  65536
#define NCODE 1024
#define PATCH 48
#define CAND_CAP (1<<22)
#define TAU 4e-3f

__device__ float g_Wcomb[PATCH*CD];
__device__ float g_bcomb[CD];
__device__ float g_cnorm[NCODE];
__device__ float g_cb2[NCODE*CD];
__device__ float g_cb3[NCODE*PATCH];
__device__ float g_z[NPIX*CD];
__device__ __nv_bfloat16 g_zh[NPIX*CD];
__device__ __nv_bfloat16 g_cbh[NCODE*CD];
__device__ float g_znpart[NPIX*4];
__device__ float g_znorm[NPIX];
__device__ float g_dmin[NPIX];
__device__ int   g_idx[NPIX];
__device__ float g_idxf_dummy[NPIX];
__device__ float g_part[256];
__device__ unsigned long long g_key[NPIX];
__device__ unsigned int g_cand[CAND_CAP];
__device__ int g_ncand;

__device__ __forceinline__ uint32_t bf2pack(float lo, float hi){
    uint32_t r; asm("cvt.rn.bf16x2.f32 %0, %1, %2;" : "=r"(r) : "f"(hi), "f"(lo)); return r;
}
__device__ __forceinline__ unsigned encf(float f){
    unsigned b = __float_as_uint(f);
    return (b & 0x80000000u) ? ~b : (b | 0x80000000u);
}
__device__ __forceinline__ float decf(unsigned u){
    return __uint_as_float((u & 0x80000000u) ? (u ^ 0x80000000u) : ~u);
}
__device__ __forceinline__ uint32_t cvta_s(const void* p){
    uint32_t a; asm("{ .reg .u64 t; cvta.to.shared.u64 t, %1; cvt.u32.u64 %0, t; }":"=r"(a):"l"(p)); return a;
}
#define LDM_X4(R0,R1,R2,R3,ADDR) \
    asm volatile("ldmatrix.sync.aligned.m8n8.x4.shared.b16 {%0,%1,%2,%3}, [%4];" \
        : "=r"(R0), "=r"(R1), "=r"(R2), "=r"(R3) : "r"(ADDR))

// merged: comb (blocks 0-48), cnorm (49-52), cbh (53-1076)
__global__ void k_prep(const float* __restrict__ enc_w, const float* __restrict__ enc_b,
                       const float* __restrict__ w1, const float* __restrict__ b1,
                       const float* __restrict__ cb){
    int bx = blockIdx.x, t = threadIdx.x;
    if (bx < 49) {
        int c = t, p = bx;
        if (p < PATCH) {
            float s = 0.f;
            for (int o = 0; o < CD; ++o) s += enc_w[o*PATCH+p] * w1[c*CD+o];
            g_Wcomb[p*CD+c] = s;
        } else {
            float s = b1[c];
            for (int o = 0; o < CD; ++o) s += enc_b[o] * w1[c*CD+o];
            g_bcomb[c] = s;
        }
    } else if (bx < 53) {
        int k = (bx-49)*256 + t;
        const float* r = cb + k*CD; float s = 0.f;
        for (int j = 0; j < CD; j += 4) {
            float4 v = *(const float4*)(r+j);
            s += v.x*v.x + v.y*v.y + v.z*v.z + v.w*v.w;
        }
        g_cnorm[k] = s;
    } else {
        int i = (bx-53)*256 + t;
        g_cbh[i] = __float2bfloat16(cb[i]);
    }
}

// cb2: 1024x256x256, 32x64 tiles, 128 CTAs
__global__ void k_cb2(const float* __restrict__ A, const float* __restrict__ B,
                      const float* __restrict__ bias){
    __shared__ float As[32][17]; __shared__ float Bs[16][65];
    int t = threadIdx.x, tx = t & 15, ty = t >> 4;
    int m0 = blockIdx.x*32, n0 = blockIdx.y*64;
    float acc[2][4] = {};
    for (int kt = 0; kt < 256; kt += 16) {
        if (t < 128) {
            int row = t>>2, q = t&3;
            float4 v = *(const float4*)&A[(m0+row)*256 + kt + q*4];
            As[row][q*4]=v.x; As[row][q*4+1]=v.y; As[row][q*4+2]=v.z; As[row][q*4+3]=v.w;
        }
        {
            int row = t>>2, q = t&3;
            float4 w = *(const float4*)&B[(n0+row)*256 + kt + q*4];
            Bs[q*4][row]=w.x; Bs[q*4+1][row]=w.y; Bs[q*4+2][row]=w.z; Bs[q*4+3][row]=w.w;
        }
        __syncthreads();
        #pragma unroll
        for (int kk = 0; kk < 16; ++kk) {
            float a[2], b[4];
            a[0] = As[ty*2][kk]; a[1] = As[ty*2+1][kk];
            #pragma unroll
            for (int j = 0; j < 4; ++j) b[j] = Bs[kk][tx*4+j];
            #pragma unroll
            for (int i = 0; i < 2; ++i)
                #pragma unroll
                for (int j = 0; j < 4; ++j) acc[i][j] += a[i]*b[j];
        }
        __syncthreads();
    }
    #pragma unroll
    for (int i = 0; i < 2; ++i)
        #pragma unroll
        for (int j = 0; j < 4; ++j)
            g_cb2[(m0+ty*2+i)*256 + n0+tx*4+j] = acc[i][j] + bias[n0+tx*4+j];
}

__global__ void k_cb3(const float* __restrict__ dec_w){
    __shared__ float row[CD];
    int k = blockIdx.x, t = threadIdx.x;
    for (int c = t; c < CD; c += 192) row[c] = g_cb2[k*CD+c];
    __syncthreads();
    int q = t>>2, part = t&3;
    int o = q>>4, rr = q&15, ki = rr>>2, kj = rr&3;
    int qf = o*16 + (3-ki)*4 + (3-kj);
    float s = 0.f;
    for (int c = part; c < CD; c += 4) s += row[c] * dec_w[c*PATCH+qf];
    s += __shfl_down_sync(0xffffffffu, s, 2, 4);
    s += __shfl_down_sync(0xffffffffu, s, 1, 4);
    if (!part) g_cb3[k*PATCH+q] = s;
}

__global__ void k_z(const float* __restrict__ x){
    __shared__ float Ps[64][49]; __shared__ float Ws[48][65];
    int tx = threadIdx.x & 15, ty = threadIdx.x >> 4;
    int m0 = blockIdx.x*64, n0 = blockIdx.y*64;
    for (int e = threadIdx.x; e < 768; e += 256) {
        int pix = e/12, r = e - pix*12;
        int n = m0+pix, b = n>>12, rem = n&4095, i = rem>>6, j = rem&63;
        int cin = r>>2, ki = r&3;
        float4 v = *(const float4*)&x[(((b*3+cin)<<8) + (i*4+ki))*256 + j*4];
        Ps[pix][r*4]=v.x; Ps[pix][r*4+1]=v.y; Ps[pix][r*4+2]=v.z; Ps[pix][r*4+3]=v.w;
    }
    for (int e = threadIdx.x; e < 768; e += 256) {
        int row = e>>4, q = e&15;
        float4 v = *(const float4*)&g_Wcomb[row*CD + n0 + q*4];
        Ws[row][q*4]=v.x; Ws[row][q*4+1]=v.y; Ws[row][q*4+2]=v.z; Ws[row][q*4+3]=v.w;
    }
    __syncthreads();
    float acc[4][4] = {};
    #pragma unroll 8
    for (int k = 0; k < 48; ++k) {
        float a[4], b[4];
        #pragma unroll
        for (int i = 0; i < 4; ++i) a[i] = Ps[ty*4+i][k];
        #pragma unroll
        for (int j = 0; j < 4; ++j) b[j] = Ws[k][tx*4+j];
        #pragma unroll
        for (int i = 0; i < 4; ++i)
            #pragma unroll
            for (int j = 0; j < 4; ++j) acc[i][j] += a[i]*b[j];
    }
    float b0 = g_bcomb[n0+tx*4], b1 = g_bcomb[n0+tx*4+1];
    float b2 = g_bcomb[n0+tx*4+2], b3 = g_bcomb[n0+tx*4+3];
    #pragma unroll
    for (int i = 0; i < 4; ++i) {
        size_t row = m0+ty*4+i;
        float4 o = make_float4(acc[i][0]+b0, acc[i][1]+b1, acc[i][2]+b2, acc[i][3]+b3);
        *(float4*)&g_z[row*CD + n0+tx*4] = o;
        *(uint2*)(g_zh + row*CD + n0+tx*4) = make_uint2(bf2pack(o.x,o.y), bf2pack(o.z,o.w));
        float s = o.x*o.x + o.y*o.y + o.z*o.z + o.w*o.w;
        s += __shfl_down_sync(0xffffffffu, s, 8, 16);
        s += __shfl_down_sync(0xffffffffu, s, 4, 16);
        s += __shfl_down_sync(0xffffffffu, s, 2, 16);
        s += __shfl_down_sync(0xffffffffu, s, 1, 16);
        if (!tx) g_znpart[row*4 + blockIdx.y] = s;
    }
}

__global__ void k_znorm2(){
    int n = blockIdx.x*256 + threadIdx.x;
    float4 p = *(const float4*)&g_znpart[n*4];
    g_znorm[n] = ((p.x + p.y) + p.z) + p.w;
}

__global__ void k_reset(){
    int n = blockIdx.x*256 + threadIdx.x;
    g_key[n] = ~0ull;
    if (n == 0) g_ncand = 0;
}

// ---- HMMA approx scores; pipelined B prefetch + ldmatrix fragments ----
#define SS_STRIDE 1032
#define AS_STRIDE 264
#define BS_STRIDE 72
#define AS_OFF 132096
#define BS_OFF (AS_OFF + 64*AS_STRIDE*2)
#define RM_OFF (BS_OFF + 256*BS_STRIDE*2)
#define SC_SMEM (RM_OFF + 256)

__device__ __forceinline__ void fetchB(uint4* pf, int tid, int cp, int kc){
    #pragma unroll
    for (int u = 0; u < 8; ++u) {
        int tt = tid + u*256, row = tt>>3, q = tt&7;
        pf[u] = *((const uint4*)(g_cbh + (size_t)(cp*256+row)*CD + kc*64) + q);
    }
}

__global__ void __launch_bounds__(256,1) k_score(){
    extern __shared__ char smraw[];
    __nv_bfloat16* Ss = (__nv_bfloat16*)smraw;
    __nv_bfloat16* As = (__nv_bfloat16*)(smraw + AS_OFF);
    __nv_bfloat16* Bs = (__nv_bfloat16*)(smraw + BS_OFF);
    unsigned* RM = (unsigned*)(smraw + RM_OFF);
    int tid = threadIdx.x, w = tid>>5, lane = tid&31;
    int grp = lane>>2, tig = lane&3;
    int lr = lane&7, lm = lane>>3;
    int r0 = blockIdx.x*64;
    if (tid < 64) RM[tid] = 0u;
    for (int t = tid; t < 2048; t += 256) {
        int row = t>>5, q = t&31;
        *(uint4*)(As + row*AS_STRIDE + q*8) = *((const uint4*)(g_zh + (size_t)(r0+row)*CD) + q);
    }
    uint32_t As_sm = cvta_s(As), Bs_sm = cvta_s(Bs);
    uint32_t aBase = As_sm + (uint32_t)((((lm&1)*8 + lr)*AS_STRIDE + (lm>>1)*8)*2);
    uint32_t bBase = Bs_sm + (uint32_t)(((w*32 + (lm>>1)*8 + lr)*BS_STRIDE + (lm&1)*8)*2);
    unsigned lmax[8];
    #pragma unroll
    for (int i = 0; i < 8; ++i) lmax[i] = 0u;
    uint4 pf[8];
    fetchB(pf, tid, 0, 0);

    for (int cp = 0; cp < 4; ++cp) {
        float acc[4][4][4];
        #pragma unroll
        for (int i = 0; i < 4; ++i)
            #pragma unroll
            for (int j = 0; j < 4; ++j)
                #pragma unroll
                for (int q = 0; q < 4; ++q) acc[i][j][q] = 0.f;
        for (int kc = 0; kc < 4; ++kc) {
            __syncthreads();
            #pragma unroll
            for (int u = 0; u < 8; ++u) {
                int tt = tid + u*256, row = tt>>3, q = tt&7;
                *(uint4*)(Bs + row*BS_STRIDE + q*8) = pf[u];
            }
            int ch = cp*4 + kc + 1;
            if (ch < 16) fetchB(pf, tid, ch>>2, ch&3);
            __syncthreads();
            #pragma unroll
            for (int k16 = 0; k16 < 4; ++k16) {
                uint32_t a[4][4], bp[2][4];
                #pragma unroll
                for (int i = 0; i < 4; ++i)
                    LDM_X4(a[i][0], a[i][1], a[i][2], a[i][3],
                           aBase + (uint32_t)((i*16*AS_STRIDE + kc*64 + k16*16)*2));
                #pragma unroll
                for (int jp = 0; jp < 2; ++jp)
                    LDM_X4(bp[jp][0], bp[jp][1], bp[jp][2], bp[jp][3],
                           bBase + (uint32_t)((jp*16*BS_STRIDE + k16*16)*2));
                #pragma unroll
                for (int i = 0; i < 4; ++i)
                    #pragma unroll
                    for (int j = 0; j < 4; ++j)
                        asm volatile(
                            "mma.sync.aligned.m16n8k16.row.col.f32.bf16.bf16.f32 "
                            "{%0,%1,%2,%3}, {%4,%5,%6,%7}, {%8,%9}, {%0,%1,%2,%3};"
                            : "+f"(acc[i][j][0]), "+f"(acc[i][j][1]),
                              "+f"(acc[i][j][2]), "+f"(acc[i][j][3])
                            : "r"(a[i][0]), "r"(a[i][1]), "r"(a[i][2]), "r"(a[i][3]),
                              "r"(bp[j>>1][(j&1)*2]), "r"(bp[j>>1][(j&1)*2+1]));
            }
        }
        #pragma unroll
        for (int i = 0; i < 4; ++i)
            #pragma unroll
            for (int j = 0; j < 4; ++j) {
                int c_lo = cp*256 + w*32 + j*8 + tig*2;
                float cn0 = 0.5f*g_cnorm[c_lo], cn1 = 0.5f*g_cnorm[c_lo+1];
                float s00 = acc[i][j][0] - cn0, s01 = acc[i][j][1] - cn1;
                float s10 = acc[i][j][2] - cn0, s11 = acc[i][j][3] - cn1;
                int rlo = i*16+grp, rhi = rlo+8;
                *(uint32_t*)(Ss + rlo*SS_STRIDE + c_lo) = bf2pack(s00, s01);
                *(uint32_t*)(Ss + rhi*SS_STRIDE + c_lo) = bf2pack(s10, s11);
                lmax[i*2]   = max(lmax[i*2],   encf(fmaxf(s00, s01)));
                lmax[i*2+1] = max(lmax[i*2+1], encf(fmaxf(s10, s11)));
            }
    }
    #pragma unroll
    for (int i = 0; i < 4; ++i) {
        atomicMax(&RM[i*16+grp],   lmax[i*2]);
        atomicMax(&RM[i*16+8+grp], lmax[i*2+1]);
    }
    __syncthreads();
    int row = tid>>2, cbase = (tid&3)*256;
    float thr = decf(RM[row]) - TAU;
    const uint4* sp = (const uint4*)(Ss + row*SS_STRIDE + cbase);
    int cnt = 0;
    for (int it = 0; it < 32; ++it) {
        uint4 v = sp[it];
        uint32_t ws[4] = {v.x, v.y, v.z, v.w};
        #pragma unroll
        for (int h = 0; h < 4; ++h) {
            if (__uint_as_float(ws[h] << 16) >= thr) ++cnt;
            if (__uint_as_float(ws[h] & 0xffff0000u) >= thr) ++cnt;
        }
    }
    int incl = cnt;
    #pragma unroll
    for (int o = 1; o < 32; o <<= 1) {
        int t2 = __shfl_up_sync(0xffffffffu, incl, o);
        if (lane >= o) incl += t2;
    }
    int total = __shfl_sync(0xffffffffu, incl, 31);
    int base = 0;
    if (lane == 31 && total) base = atomicAdd(&g_ncand, total);
    base = __shfl_sync(0xffffffffu, base, 31);
    int pos = base + incl - cnt;
    if (total) {
        for (int it = 0; it < 32; ++it) {
            uint4 v = sp[it];
            uint32_t ws[4] = {v.x, v.y, v.z, v.w};
            #pragma unroll
            for (int h = 0; h < 4; ++h) {
                int c = cbase + it*8 + h*2;
                if (__uint_as_float(ws[h] << 16) >= thr) {
                    if (pos < CAND_CAP) g_cand[pos] = ((unsigned)(r0+row)<<10) | c;
                    ++pos;
                }
                if (__uint_as_float(ws[h] & 0xffff0000u) >= thr) {
                    if (pos < CAND_CAP) g_cand[pos] = ((unsigned)(r0+row)<<10) | (c+1);
                    ++pos;
                }
            }
        }
    }
}

__global__ void k_pick2(const float* __restrict__ cb){
    int total = g_ncand; if (total > CAND_CAP) total = CAND_CAP;
    for (int i = blockIdx.x*blockDim.x + threadIdx.x; i < total; i += gridDim.x*blockDim.x) {
        unsigned e = g_cand[i];
        int n = (int)(e>>10), code = (int)(e & 1023u);
        const float4* zp = (const float4*)(g_z + (size_t)n*CD);
        const float4* cp = (const float4*)(cb + (size_t)code*CD);
        float m = 0.f;
        #pragma unroll 8
        for (int q = 0; q < 64; ++q) {
            float4 a = zp[q], b = cp[q];
            m = __fmaf_rn(a.x,b.x,m); m = __fmaf_rn(a.y,b.y,m);
            m = __fmaf_rn(a.z,b.z,m); m = __fmaf_rn(a.w,b.w,m);
        }
        float t = __fadd_rn(g_znorm[n], -__fadd_rn(m,m));
        float d = __fadd_rn(t, g_cnorm[code]);
        unsigned long long key = ((unsigned long long)__float_as_uint(d)<<32) | (unsigned)code;
        atomicMin(&g_key[n], key);
    }
}

__global__ void k_pick3(float* __restrict__ idx_out){
    int n = blockIdx.x*256 + threadIdx.x;
    unsigned long long k = g_key[n];
    int bi = (int)(k & 0xffffffffu);
    g_idx[n] = bi;
    g_dmin[n] = __uint_as_float((unsigned)(k>>32));
    float* op = idx_out ? idx_out : g_idxf_dummy;
    op[n] = (float)bi;
}

__global__ void k_decode(const float* __restrict__ dec_b, float* __restrict__ out){
    int t = blockIdx.x*256 + threadIdx.x;
    int v = t<<2;
    int j = (v>>2)&63, y = (v>>8)&255, bo = v>>16;
    int b = bo/3, o = bo - b*3, i = y>>2, ki = y&3;
    int n = (b<<12) + (i<<6) + j;
    int id = g_idx[n];
    float4 w = *(const float4*)&g_cb3[id*PATCH + o*16 + (ki<<2)];
    float bb = dec_b[o];
    ((float4*)out)[t] = make_float4(w.x+bb, w.y+bb, w.z+bb, w.w+bb);
}

__global__ void k_loss1(){
    __shared__ float sm[256]; int t = threadIdx.x;
    sm[t] = g_dmin[blockIdx.x*256 + t]; __syncthreads();
    for (int s = 128; s; s >>= 1) { if (t < s) sm[t] += sm[t+s]; __syncthreads(); }
    if (!t) g_part[blockIdx.x] = sm[0];
}
__global__ void k_loss2(float* __restrict__ lo){
    __shared__ float sm[256]; int t = threadIdx.x;
    sm[t] = g_part[t]; __syncthreads();
    for (int s = 128; s; s >>= 1) { if (t < s) sm[t] += sm[t+s]; __syncthreads(); }
    if (!t) *lo = 1.25f * sm[0] / 16777216.0f;
}

extern "C" void kernel_launch(void* const* d_in, const int* in_sizes, int n_in,
                              void* d_out, int out_size){
    const float* x     = (const float*)d_in[0];
    const float* enc_w = (const float*)d_in[1];
    const float* enc_b = (const float*)d_in[2];
    const float* w1    = (const float*)d_in[3];
    const float* b1    = (const float*)d_in[4];
    const float* cb    = (const float*)d_in[5];
    const float* w2    = (const float*)d_in[6];
    const float* b2    = (const float*)d_in[7];
    const float* dw    = (const float*)d_in[8];
    const float* db    = (const float*)d_in[9];
    float* out = (float*)d_out;

    static bool attr_done = false;
    if (!attr_done) {
        cudaFuncSetAttribute(k_score, cudaFuncAttributeMaxDynamicSharedMemorySize, SC_SMEM);
        attr_done = true;
    }

    k_prep <<<1077, 256>>>(enc_w, enc_b, w1, b1, cb);
    k_cb2  <<<dim3(32,4), 256>>>(cb, w2, b2);
    k_cb3  <<<1024, 192>>>(dw);
    k_z    <<<dim3(1024,4), 256>>>(x);
    k_znorm2<<<256, 256>>>();
    k_reset<<<256, 256>>>();
    k_score<<<1024, 256, SC_SMEM>>>();
    k_pick2<<<2048, 128>>>(cb);

    bool has_idx  = out_size >= 3145728 + 65536;
    bool has_loss = out_size >= 3145728 + 65536 + 1;
    k_pick3<<<256, 256>>>(has_idx ? out + 3145728 : nullptr);
    k_decode<<<3072, 256>>>(db, out);
    if (has_loss) {
        k_loss1<<<256, 256>>>();
        k_loss2<<<1, 256>>>(out + 3145728 + 65536);
    }
}

// round 9
// speedup vs baseline: 2.2802x; 1.0263x over previous
#include <cuda_runtime.h>
#include <cuda_bf16.h>
#include <cstdint>
#include <math_constants.h>

#define CD    256
#define NPIX  65536
#define NCODE 1024
#define PATCH 48
#define CAND_CAP (1<<22)
#define TAU 4e-3f

__device__ float g_Wcomb[PATCH*CD];
__device__ float g_bcomb[CD];
__device__ float g_cnorm[NCODE];
__device__ float g_cb2[NCODE*CD];
__device__ float g_cb3[NCODE*PATCH];
__device__ float g_z[NPIX*CD];
__device__ __nv_bfloat16 g_zh[NPIX*CD];
__device__ __nv_bfloat16 g_cbh[NCODE*CD];
__device__ float g_znpart[NPIX*4];
__device__ float g_znorm[NPIX];
__device__ int   g_idx[NPIX];
__device__ float g_idxf_dummy[NPIX];
__device__ float g_part[256];
__device__ unsigned long long g_key[NPIX];
__device__ unsigned int g_cand[CAND_CAP];
__device__ int g_ncand;

__device__ __forceinline__ uint32_t bf2pack(float lo, float hi){
    uint32_t r; asm("cvt.rn.bf16x2.f32 %0, %1, %2;" : "=r"(r) : "f"(hi), "f"(lo)); return r;
}
__device__ __forceinline__ unsigned encf(float f){
    unsigned b = __float_as_uint(f);
    return (b & 0x80000000u) ? ~b : (b | 0x80000000u);
}
__device__ __forceinline__ float decf(unsigned u){
    return __uint_as_float((u & 0x80000000u) ? (u ^ 0x80000000u) : ~u);
}
__device__ __forceinline__ uint32_t cvta_s(const void* p){
    uint32_t a; asm("{ .reg .u64 t; cvta.to.shared.u64 t, %1; cvt.u32.u64 %0, t; }":"=r"(a):"l"(p)); return a;
}
#define LDM_X4(R0,R1,R2,R3,ADDR) \
    asm volatile("ldmatrix.sync.aligned.m8n8.x4.shared.b16 {%0,%1,%2,%3}, [%4];" \
        : "=r"(R0), "=r"(R1), "=r"(R2), "=r"(R3) : "r"(ADDR))

__global__ void k_prep(const float* __restrict__ enc_w, const float* __restrict__ enc_b,
                       const float* __restrict__ w1, const float* __restrict__ b1,
                       const float* __restrict__ cb){
    int bx = blockIdx.x, t = threadIdx.x;
    if (bx < 49) {
        int c = t, p = bx;
        if (p < PATCH) {
            float s = 0.f;
            for (int o = 0; o < CD; ++o) s += enc_w[o*PATCH+p] * w1[c*CD+o];
            g_Wcomb[p*CD+c] = s;
        } else {
            float s = b1[c];
            for (int o = 0; o < CD; ++o) s += enc_b[o] * w1[c*CD+o];
            g_bcomb[c] = s;
        }
    } else if (bx < 53) {
        int k = (bx-49)*256 + t;
        const float* r = cb + k*CD; float s = 0.f;
        for (int j = 0; j < CD; j += 4) {
            float4 v = *(const float4*)(r+j);
            s += v.x*v.x + v.y*v.y + v.z*v.z + v.w*v.w;
        }
        g_cnorm[k] = s;
    } else {
        int i = (bx-53)*256 + t;
        g_cbh[i] = __float2bfloat16(cb[i]);
    }
}

__global__ void k_cb2(const float* __restrict__ A, const float* __restrict__ B,
                      const float* __restrict__ bias){
    __shared__ float As[32][17]; __shared__ float Bs[16][68];
    int t = threadIdx.x, tx = t & 15, ty = t >> 4;
    int m0 = blockIdx.x*32, n0 = blockIdx.y*64;
    float acc[2][4] = {};
    for (int kt = 0; kt < 256; kt += 16) {
        if (t < 128) {
            int row = t>>2, q = t&3;
            float4 v = *(const float4*)&A[(m0+row)*256 + kt + q*4];
            As[row][q*4]=v.x; As[row][q*4+1]=v.y; As[row][q*4+2]=v.z; As[row][q*4+3]=v.w;
        }
        {
            int row = t>>2, q = t&3;
            float4 w = *(const float4*)&B[(n0+row)*256 + kt + q*4];
            Bs[q*4][row]=w.x; Bs[q*4+1][row]=w.y; Bs[q*4+2][row]=w.z; Bs[q*4+3][row]=w.w;
        }
        __syncthreads();
        #pragma unroll
        for (int kk = 0; kk < 16; ++kk) {
            float a0 = As[ty*2][kk], a1 = As[ty*2+1][kk];
            float4 b = *(const float4*)&Bs[kk][tx*4];
            acc[0][0] += a0*b.x; acc[0][1] += a0*b.y; acc[0][2] += a0*b.z; acc[0][3] += a0*b.w;
            acc[1][0] += a1*b.x; acc[1][1] += a1*b.y; acc[1][2] += a1*b.z; acc[1][3] += a1*b.w;
        }
        __syncthreads();
    }
    #pragma unroll
    for (int i = 0; i < 2; ++i)
        #pragma unroll
        for (int j = 0; j < 4; ++j)
            g_cb2[(m0+ty*2+i)*256 + n0+tx*4+j] = acc[i][j] + bias[n0+tx*4+j];
}

__global__ void k_cb3(const float* __restrict__ dec_w){
    __shared__ float row[CD];
    int k = blockIdx.x, t = threadIdx.x;
    for (int c = t; c < CD; c += 192) row[c] = g_cb2[k*CD+c];
    __syncthreads();
    int q = t>>2, part = t&3;
    int o = q>>4, rr = q&15, ki = rr>>2, kj = rr&3;
    int qf = o*16 + (3-ki)*4 + (3-kj);
    float s = 0.f;
    for (int c = part; c < CD; c += 4) s += row[c] * dec_w[c*PATCH+qf];
    s += __shfl_down_sync(0xffffffffu, s, 2, 4);
    s += __shfl_down_sync(0xffffffffu, s, 1, 4);
    if (!part) g_cb3[k*PATCH+q] = s;
}

// z GEMM: transposed patch tile + stride-68 pads -> 2x LDS.128 per k-step
__global__ void k_z(const float* __restrict__ x){
    __shared__ float Pt[48][68]; __shared__ float Ws[48][68];
    int tx = threadIdx.x & 15, ty = threadIdx.x >> 4;
    int m0 = blockIdx.x*64, n0 = blockIdx.y*64;
    for (int e = threadIdx.x; e < 768; e += 256) {
        int pix = e/12, r = e - pix*12;
        int n = m0+pix, b = n>>12, rem = n&4095, i = rem>>6, j = rem&63;
        int cin = r>>2, ki = r&3;
        float4 v = *(const float4*)&x[(((b*3+cin)<<8) + (i*4+ki))*256 + j*4];
        Pt[r*4][pix]=v.x; Pt[r*4+1][pix]=v.y; Pt[r*4+2][pix]=v.z; Pt[r*4+3][pix]=v.w;
    }
    for (int e = threadIdx.x; e < 768; e += 256) {
        int row = e>>4, q = e&15;
        *(float4*)&Ws[row][q*4] = *(const float4*)&g_Wcomb[row*CD + n0 + q*4];
    }
    __syncthreads();
    float acc[4][4] = {};
    #pragma unroll 8
    for (int k = 0; k < 48; ++k) {
        float4 a = *(const float4*)&Pt[k][ty*4];
        float4 b = *(const float4*)&Ws[k][tx*4];
        float av[4] = {a.x,a.y,a.z,a.w}, bv[4] = {b.x,b.y,b.z,b.w};
        #pragma unroll
        for (int i = 0; i < 4; ++i)
            #pragma unroll
            for (int j = 0; j < 4; ++j) acc[i][j] += av[i]*bv[j];
    }
    float b0 = g_bcomb[n0+tx*4], b1 = g_bcomb[n0+tx*4+1];
    float b2 = g_bcomb[n0+tx*4+2], b3 = g_bcomb[n0+tx*4+3];
    #pragma unroll
    for (int i = 0; i < 4; ++i) {
        size_t row = m0+ty*4+i;
        float4 o = make_float4(acc[i][0]+b0, acc[i][1]+b1, acc[i][2]+b2, acc[i][3]+b3);
        *(float4*)&g_z[row*CD + n0+tx*4] = o;
        *(uint2*)(g_zh + row*CD + n0+tx*4) = make_uint2(bf2pack(o.x,o.y), bf2pack(o.z,o.w));
        float s = o.x*o.x + o.y*o.y + o.z*o.z + o.w*o.w;
        s += __shfl_down_sync(0xffffffffu, s, 8, 16);
        s += __shfl_down_sync(0xffffffffu, s, 4, 16);
        s += __shfl_down_sync(0xffffffffu, s, 2, 16);
        s += __shfl_down_sync(0xffffffffu, s, 1, 16);
        if (!tx) g_znpart[row*4 + blockIdx.y] = s;
    }
}

__global__ void k_misc(){
    int n = blockIdx.x*256 + threadIdx.x;
    float4 p = *(const float4*)&g_znpart[n*4];
    g_znorm[n] = ((p.x + p.y) + p.z) + p.w;
    g_key[n] = ~0ull;
    if (n == 0) g_ncand = 0;
}

// ---- HMMA approx scores; pipelined B prefetch + ldmatrix ----
#define SS_STRIDE 1032
#define AS_STRIDE 264
#define BS_STRIDE 72
#define AS_OFF 132096
#define BS_OFF (AS_OFF + 64*AS_STRIDE*2)
#define RM_OFF (BS_OFF + 256*BS_STRIDE*2)
#define SC_SMEM (RM_OFF + 256)

__device__ __forceinline__ void fetchB(uint4* pf, int tid, int cp, int kc){
    #pragma unroll
    for (int u = 0; u < 8; ++u) {
        int tt = tid + u*256, row = tt>>3, q = tt&7;
        pf[u] = *((const uint4*)(g_cbh + (size_t)(cp*256+row)*CD + kc*64) + q);
    }
}

__global__ void __launch_bounds__(256,1) k_score(){
    extern __shared__ char smraw[];
    __nv_bfloat16* Ss = (__nv_bfloat16*)smraw;
    __nv_bfloat16* As = (__nv_bfloat16*)(smraw + AS_OFF);
    __nv_bfloat16* Bs = (__nv_bfloat16*)(smraw + BS_OFF);
    unsigned* RM = (unsigned*)(smraw + RM_OFF);
    int tid = threadIdx.x, w = tid>>5, lane = tid&31;
    int grp = lane>>2, tig = lane&3;
    int lr = lane&7, lm = lane>>3;
    int r0 = blockIdx.x*64;
    if (tid < 64) RM[tid] = 0u;
    for (int t = tid; t < 2048; t += 256) {
        int row = t>>5, q = t&31;
        *(uint4*)(As + row*AS_STRIDE + q*8) = *((const uint4*)(g_zh + (size_t)(r0+row)*CD) + q);
    }
    uint32_t As_sm = cvta_s(As), Bs_sm = cvta_s(Bs);
    uint32_t aBase = As_sm + (uint32_t)((((lm&1)*8 + lr)*AS_STRIDE + (lm>>1)*8)*2);
    uint32_t bBase = Bs_sm + (uint32_t)(((w*32 + (lm>>1)*8 + lr)*BS_STRIDE + (lm&1)*8)*2);
    unsigned lmax[8];
    #pragma unroll
    for (int i = 0; i < 8; ++i) lmax[i] = 0u;
    uint4 pf[8];
    fetchB(pf, tid, 0, 0);

    for (int cp = 0; cp < 4; ++cp) {
        float acc[4][4][4];
        #pragma unroll
        for (int i = 0; i < 4; ++i)
            #pragma unroll
            for (int j = 0; j < 4; ++j)
                #pragma unroll
                for (int q = 0; q < 4; ++q) acc[i][j][q] = 0.f;
        for (int kc = 0; kc < 4; ++kc) {
            __syncthreads();
            #pragma unroll
            for (int u = 0; u < 8; ++u) {
                int tt = tid + u*256, row = tt>>3, q = tt&7;
                *(uint4*)(Bs + row*BS_STRIDE + q*8) = pf[u];
            }
            int ch = cp*4 + kc + 1;
            if (ch < 16) fetchB(pf, tid, ch>>2, ch&3);
            __syncthreads();
            #pragma unroll
            for (int k16 = 0; k16 < 4; ++k16) {
                uint32_t a[4][4], bp[2][4];
                #pragma unroll
                for (int i = 0; i < 4; ++i)
                    LDM_X4(a[i][0], a[i][1], a[i][2], a[i][3],
                           aBase + (uint32_t)((i*16*AS_STRIDE + kc*64 + k16*16)*2));
                #pragma unroll
                for (int jp = 0; jp < 2; ++jp)
                    LDM_X4(bp[jp][0], bp[jp][1], bp[jp][2], bp[jp][3],
                           bBase + (uint32_t)((jp*16*BS_STRIDE + k16*16)*2));
                #pragma unroll
                for (int i = 0; i < 4; ++i)
                    #pragma unroll
                    for (int j = 0; j < 4; ++j)
                        asm volatile(
                            "mma.sync.aligned.m16n8k16.row.col.f32.bf16.bf16.f32 "
                            "{%0,%1,%2,%3}, {%4,%5,%6,%7}, {%8,%9}, {%0,%1,%2,%3};"
                            : "+f"(acc[i][j][0]), "+f"(acc[i][j][1]),
                              "+f"(acc[i][j][2]), "+f"(acc[i][j][3])
                            : "r"(a[i][0]), "r"(a[i][1]), "r"(a[i][2]), "r"(a[i][3]),
                              "r"(bp[j>>1][(j&1)*2]), "r"(bp[j>>1][(j&1)*2+1]));
            }
        }
        #pragma unroll
        for (int i = 0; i < 4; ++i)
            #pragma unroll
            for (int j = 0; j < 4; ++j) {
                int c_lo = cp*256 + w*32 + j*8 + tig*2;
                float cn0 = 0.5f*g_cnorm[c_lo], cn1 = 0.5f*g_cnorm[c_lo+1];
                float s00 = acc[i][j][0] - cn0, s01 = acc[i][j][1] - cn1;
                float s10 = acc[i][j][2] - cn0, s11 = acc[i][j][3] - cn1;
                int rlo = i*16+grp, rhi = rlo+8;
                *(uint32_t*)(Ss + rlo*SS_STRIDE + c_lo) = bf2pack(s00, s01);
                *(uint32_t*)(Ss + rhi*SS_STRIDE + c_lo) = bf2pack(s10, s11);
                lmax[i*2]   = max(lmax[i*2],   encf(fmaxf(s00, s01)));
                lmax[i*2+1] = max(lmax[i*2+1], encf(fmaxf(s10, s11)));
            }
    }
    #pragma unroll
    for (int i = 0; i < 4; ++i) {
        atomicMax(&RM[i*16+grp],   lmax[i*2]);
        atomicMax(&RM[i*16+8+grp], lmax[i*2+1]);
    }
    __syncthreads();
    int row = tid>>2, cbase = (tid&3)*256;
    float thr = decf(RM[row]) - TAU;
    const uint4* sp = (const uint4*)(Ss + row*SS_STRIDE + cbase);
    int cnt = 0;
    for (int it = 0; it < 32; ++it) {
        uint4 v = sp[it];
        uint32_t ws[4] = {v.x, v.y, v.z, v.w};
        #pragma unroll
        for (int h = 0; h < 4; ++h) {
            if (__uint_as_float(ws[h] << 16) >= thr) ++cnt;
            if (__uint_as_float(ws[h] & 0xffff0000u) >= thr) ++cnt;
        }
    }
    int incl = cnt;
    #pragma unroll
    for (int o = 1; o < 32; o <<= 1) {
        int t2 = __shfl_up_sync(0xffffffffu, incl, o);
        if (lane >= o) incl += t2;
    }
    int total = __shfl_sync(0xffffffffu, incl, 31);
    int base = 0;
    if (lane == 31 && total) base = atomicAdd(&g_ncand, total);
    base = __shfl_sync(0xffffffffu, base, 31);
    int pos = base + incl - cnt;
    if (total) {
        for (int it = 0; it < 32; ++it) {
            uint4 v = sp[it];
            uint32_t ws[4] = {v.x, v.y, v.z, v.w};
            #pragma unroll
            for (int h = 0; h < 4; ++h) {
                int c = cbase + it*8 + h*2;
                if (__uint_as_float(ws[h] << 16) >= thr) {
                    if (pos < CAND_CAP) g_cand[pos] = ((unsigned)(r0+row)<<10) | c;
                    ++pos;
                }
                if (__uint_as_float(ws[h] & 0xffff0000u) >= thr) {
                    if (pos < CAND_CAP) g_cand[pos] = ((unsigned)(r0+row)<<10) | (c+1);
                    ++pos;
                }
            }
        }
    }
}

__global__ void k_pick2(const float* __restrict__ cb){
    int total = g_ncand; if (total > CAND_CAP) total = CAND_CAP;
    for (int i = blockIdx.x*blockDim.x + threadIdx.x; i < total; i += gridDim.x*blockDim.x) {
        unsigned e = g_cand[i];
        int n = (int)(e>>10), code = (int)(e & 1023u);
        const float4* zp = (const float4*)(g_z + (size_t)n*CD);
        const float4* cp = (const float4*)(cb + (size_t)code*CD);
        float m = 0.f;
        #pragma unroll 8
        for (int q = 0; q < 64; ++q) {
            float4 a = zp[q], b = cp[q];
            m = __fmaf_rn(a.x,b.x,m); m = __fmaf_rn(a.y,b.y,m);
            m = __fmaf_rn(a.z,b.z,m); m = __fmaf_rn(a.w,b.w,m);
        }
        float t = __fadd_rn(g_znorm[n], -__fadd_rn(m,m));
        float d = __fadd_rn(t, g_cnorm[code]);
        unsigned long long key = ((unsigned long long)__float_as_uint(d)<<32) | (unsigned)code;
        atomicMin(&g_key[n], key);
    }
}

// pick3 + loss block-reduce (same tree order as before -> bit-identical)
__global__ void k_pick3(float* __restrict__ idx_out){
    __shared__ float sm[256];
    int t = threadIdx.x, n = blockIdx.x*256 + t;
    unsigned long long k = g_key[n];
    int bi = (int)(k & 0xffffffffu);
    g_idx[n] = bi;
    float* op = idx_out ? idx_out : g_idxf_dummy;
    op[n] = (float)bi;
    sm[t] = __uint_as_float((unsigned)(k>>32));
    __syncthreads();
    for (int s = 128; s; s >>= 1) { if (t < s) sm[t] += sm[t+s]; __syncthreads(); }
    if (!t) g_part[blockIdx.x] = sm[0];
}

__global__ void k_decode(const float* __restrict__ dec_b, float* __restrict__ out){
    int t = blockIdx.x*256 + threadIdx.x;
    int v = t<<2;
    int j = (v>>2)&63, y = (v>>8)&255, bo = v>>16;
    int b = bo/3, o = bo - b*3, i = y>>2, ki = y&3;
    int n = (b<<12) + (i<<6) + j;
    int id = g_idx[n];
    float4 w = *(const float4*)&g_cb3[id*PATCH + o*16 + (ki<<2)];
    float bb = dec_b[o];
    ((float4*)out)[t] = make_float4(w.x+bb, w.y+bb, w.z+bb, w.w+bb);
}

__global__ void k_loss2(float* __restrict__ lo){
    __shared__ float sm[256]; int t = threadIdx.x;
    sm[t] = g_part[t]; __syncthreads();
    for (int s = 128; s; s >>= 1) { if (t < s) sm[t] += sm[t+s]; __syncthreads(); }
    if (!t) *lo = 1.25f * sm[0] / 16777216.0f;
}

extern "C" void kernel_launch(void* const* d_in, const int* in_sizes, int n_in,
                              void* d_out, int out_size){
    const float* x     = (const float*)d_in[0];
    const float* enc_w = (const float*)d_in[1];
    const float* enc_b = (const float*)d_in[2];
    const float* w1    = (const float*)d_in[3];
    const float* b1    = (const float*)d_in[4];
    const float* cb    = (const float*)d_in[5];
    const float* w2    = (const float*)d_in[6];
    const float* b2    = (const float*)d_in[7];
    const float* dw    = (const float*)d_in[8];
    const float* db    = (const float*)d_in[9];
    float* out = (float*)d_out;

    static bool attr_done = false;
    if (!attr_done) {
        cudaFuncSetAttribute(k_score, cudaFuncAttributeMaxDynamicSharedMemorySize, SC_SMEM);
        attr_done = true;
    }

    k_prep <<<1077, 256>>>(enc_w, enc_b, w1, b1, cb);
    k_cb2  <<<dim3(32,4), 256>>>(cb, w2, b2);
    k_cb3  <<<1024, 192>>>(dw);
    k_z    <<<dim3(1024,4), 256>>>(x);
    k_misc <<<256, 256>>>();
    k_score<<<1024, 256, SC_SMEM>>>();
    k_pick2<<<2048, 128>>>(cb);

    bool has_idx  = out_size >= 3145728 + 65536;
    bool has_loss = out_size >= 3145728 + 65536 + 1;
    k_pick3<<<256, 256>>>(has_idx ? out + 3145728 : nullptr);
    k_decode<<<3072, 256>>>(db, out);
    if (has_loss) k_loss2<<<1, 256>>>(out + 3145728 + 65536);
}

// round 13
// speedup vs baseline: 2.8104x; 1.2326x over previous
#include <cuda_runtime.h>
#include <cuda_bf16.h>
#include <cuda_fp16.h>
#include <cstdint>
#include <math_constants.h>

#define CD    256
#define NPIX  65536
#define NCODE 1024
#define PATCH 48
#define CAND_CAP (1<<22)
#define TAU 1.5e-3f

__device__ float g_Wcomb[PATCH*CD];
__device__ float g_bcomb[CD];
__device__ float g_cnorm[NCODE];
__device__ float g_Gt[PATCH*CD];
__device__ float g_h[PATCH];
__device__ float g_cb3[NCODE*PATCH];
__device__ float g_z[NPIX*CD];
__device__ __nv_bfloat16 g_zh[NPIX*CD];
__device__ __nv_bfloat16 g_cbh[NCODE*CD];
__device__ float g_znpart[NPIX*4];
__device__ float g_znorm[NPIX];
__device__ int   g_idx[NPIX];
__device__ float g_idxf_dummy[NPIX];
__device__ float g_part[256];
__device__ unsigned long long g_key[NPIX];
__device__ unsigned int g_cand[CAND_CAP];
__device__ int g_ncand;

__device__ __forceinline__ uint32_t bf2pack(float lo, float hi){
    uint32_t r; asm("cvt.rn.bf16x2.f32 %0, %1, %2;" : "=r"(r) : "f"(hi), "f"(lo)); return r;
}
__device__ __forceinline__ uint32_t h2pack(float lo, float hi){
    __half2 h = __floats2half2_rn(lo, hi);
    return *reinterpret_cast<uint32_t*>(&h);
}
__device__ __forceinline__ unsigned encf(float f){
    unsigned b = __float_as_uint(f);
    return (b & 0x80000000u) ? ~b : (b | 0x80000000u);
}
__device__ __forceinline__ float decf(unsigned u){
    return __uint_as_float((u & 0x80000000u) ? (u ^ 0x80000000u) : ~u);
}
__device__ __forceinline__ uint32_t cvta_s(const void* p){
    uint32_t a; asm("{ .reg .u64 t; cvta.to.shared.u64 t, %1; cvt.u32.u64 %0, t; }":"=r"(a):"l"(p)); return a;
}
__device__ __forceinline__ uint64_t pk2(float a){
    uint64_t r; asm("mov.b64 %0,{%1,%1};":"=l"(r):"r"(__float_as_uint(a))); return r;
}
__device__ __forceinline__ uint64_t pk2b(float lo, float hi){
    uint64_t r; asm("mov.b64 %0,{%1,%2};":"=l"(r):"r"(__float_as_uint(lo)),"r"(__float_as_uint(hi))); return r;
}
__device__ __forceinline__ void ffma2(uint64_t& c, uint64_t a, uint64_t b){
    asm("fma.rn.f32x2 %0,%1,%2,%3;":"=l"(c):"l"(a),"l"(b),"l"(c));
}
__device__ __forceinline__ void upk2(uint64_t v, float& lo, float& hi){
    uint32_t l,h; asm("mov.b64 {%0,%1},%2;":"=r"(l),"=r"(h):"l"(v));
    lo=__uint_as_float(l); hi=__uint_as_float(h);
}
#define LDM_X4(R0,R1,R2,R3,ADDR) \
    asm volatile("ldmatrix.sync.aligned.m8n8.x4.shared.b16 {%0,%1,%2,%3}, [%4];" \
        : "=r"(R0), "=r"(R1), "=r"(R2), "=r"(R3) : "r"(ADDR))

// blocks: [0,49) comb, [49,53) cnorm, [53,1077) cbh, [1077,1333) key reset
__global__ void k_prep(const float* __restrict__ enc_w, const float* __restrict__ enc_b,
                       const float* __restrict__ w1, const float* __restrict__ b1,
                       const float* __restrict__ cb){
    int bx = blockIdx.x, t = threadIdx.x;
    if (bx < 49) {
        __shared__ float col[CD];
        int p = bx;
        col[t] = (p < PATCH) ? enc_w[t*PATCH+p] : enc_b[t];
        __syncthreads();
        int c = t;
        float s = (p < PATCH) ? 0.f : b1[c];
        for (int o = 0; o < CD; o += 4) {
            float4 wv = *(const float4*)&w1[c*CD+o];
            s = __fmaf_rn(col[o],   wv.x, s);
            s = __fmaf_rn(col[o+1], wv.y, s);
            s = __fmaf_rn(col[o+2], wv.z, s);
            s = __fmaf_rn(col[o+3], wv.w, s);
        }
        if (p < PATCH) g_Wcomb[p*CD+c] = s; else g_bcomb[c] = s;
    } else if (bx < 53) {
        int k = (bx-49)*256 + t;
        const float* r = cb + k*CD; float s = 0.f;
        for (int j = 0; j < CD; j += 4) {
            float4 v = *(const float4*)(r+j);
            s += v.x*v.x + v.y*v.y + v.z*v.z + v.w*v.w;
        }
        g_cnorm[k] = s;
    } else if (bx < 1077) {
        int i = (bx-53)*256 + t;
        g_cbh[i] = __float2bfloat16(cb[i]);
    } else {
        int n = (bx-1077)*256 + t;
        g_key[n] = ~0ull;
        if (n == 0) g_ncand = 0;
    }
}

// Gt[q][j] = sum_c w2[c][j]*dwf[c][q]; h[q] = sum_c b2[c]*dwf[c][q]
__global__ void k_G(const float* __restrict__ w2, const float* __restrict__ dw,
                    const float* __restrict__ b2){
    int q = blockIdx.x;
    if (q < PATCH) {
        int o=q>>4, rr=q&15, ki=rr>>2, kj=rr&3;
        int qf = o*16 + (3-ki)*4 + (3-kj);
        int j = threadIdx.x;
        float s = 0.f;
        for (int c = 0; c < CD; ++c) s += w2[c*CD+j]*dw[c*PATCH+qf];
        g_Gt[q*CD+j] = s;
    } else if (threadIdx.x < PATCH) {
        int t = threadIdx.x;
        int o=t>>4, rr=t&15, ki=rr>>2, kj=rr&3;
        int qf = o*16 + (3-ki)*4 + (3-kj);
        float s = 0.f;
        for (int c = 0; c < CD; ++c) s += b2[c]*dw[c*PATCH+qf];
        g_h[t] = s;
    }
}

// cb3[k][q] = cb[k] . Gt[q] + h[q]
__global__ void k_cb3(const float* __restrict__ cb){
    __shared__ float row[CD];
    int k = blockIdx.x, t = threadIdx.x;
    for (int c = t; c < CD; c += 192) row[c] = cb[k*CD+c];
    __syncthreads();
    int q = t>>2, part = t&3;
    float s = 0.f;
    for (int c = part; c < CD; c += 4) s += row[c]*g_Gt[q*CD+c];
    s += __shfl_down_sync(0xffffffffu, s, 2, 4);
    s += __shfl_down_sync(0xffffffffu, s, 1, 4);
    if (!part) g_cb3[k*PATCH+q] = s + g_h[q];
}

// z GEMM: conflict-free transposed fill + f32x2 mainloop
__global__ void k_z(const float* __restrict__ x){
    __shared__ float Pt[48][68]; __shared__ float Ws[48][68];
    int tx = threadIdx.x & 15, ty = threadIdx.x >> 4;
    int m0 = blockIdx.x*64, n0 = blockIdx.y*64;
    {
        int b = m0>>12, rem = m0&4095, i = rem>>6;
        for (int e = threadIdx.x; e < 768; e += 256) {
            int r = e>>6, pix = e&63;
            int cin = r>>2, ki = r&3;
            float4 v = *(const float4*)&x[(((b*3+cin)<<8) + (i*4+ki))*256 + pix*4];
            Pt[r*4][pix]=v.x; Pt[r*4+1][pix]=v.y; Pt[r*4+2][pix]=v.z; Pt[r*4+3][pix]=v.w;
        }
    }
    for (int e = threadIdx.x; e < 768; e += 256) {
        int row = e>>4, q = e&15;
        *(float4*)&Ws[row][q*4] = *(const float4*)&g_Wcomb[row*CD + n0 + q*4];
    }
    __syncthreads();
    uint64_t acc[4][2];
    #pragma unroll
    for (int i = 0; i < 4; ++i) { acc[i][0] = 0ull; acc[i][1] = 0ull; }
    #pragma unroll 8
    for (int k = 0; k < 48; ++k) {
        float4 a4 = *(const float4*)&Pt[k][ty*4];
        float4 b4 = *(const float4*)&Ws[k][tx*4];
        uint64_t b01 = pk2b(b4.x, b4.y), b23 = pk2b(b4.z, b4.w);
        float av[4] = {a4.x, a4.y, a4.z, a4.w};
        #pragma unroll
        for (int i = 0; i < 4; ++i) {
            uint64_t ai = pk2(av[i]);
            ffma2(acc[i][0], ai, b01);
            ffma2(acc[i][1], ai, b23);
        }
    }
    float b0 = g_bcomb[n0+tx*4], b1 = g_bcomb[n0+tx*4+1];
    float b2 = g_bcomb[n0+tx*4+2], b3 = g_bcomb[n0+tx*4+3];
    #pragma unroll
    for (int i = 0; i < 4; ++i) {
        size_t row = m0+ty*4+i;
        float a0,a1,a2,a3;
        upk2(acc[i][0], a0, a1); upk2(acc[i][1], a2, a3);
        float4 o = make_float4(a0+b0, a1+b1, a2+b2, a3+b3);
        *(float4*)&g_z[row*CD + n0+tx*4] = o;
        *(uint2*)(g_zh + row*CD + n0+tx*4) = make_uint2(bf2pack(o.x,o.y), bf2pack(o.z,o.w));
        float s = o.x*o.x + o.y*o.y + o.z*o.z + o.w*o.w;
        s += __shfl_down_sync(0xffffffffu, s, 8, 16);
        s += __shfl_down_sync(0xffffffffu, s, 4, 16);
        s += __shfl_down_sync(0xffffffffu, s, 2, 16);
        s += __shfl_down_sync(0xffffffffu, s, 1, 16);
        if (!tx) g_znpart[row*4 + blockIdx.y] = s;
    }
}

// ---- HMMA approx scores (fp16 score storage); znorm finalize at head ----
#define SS_STRIDE 1032
#define AS_STRIDE 264
#define BS_STRIDE 72
#define AS_OFF 132096
#define BS_OFF (AS_OFF + 64*AS_STRIDE*2)
#define RM_OFF (BS_OFF + 256*BS_STRIDE*2)
#define SC_SMEM (RM_OFF + 256)

__device__ __forceinline__ void fetchB(uint4* pf, int tid, int cp, int kc){
    #pragma unroll
    for (int u = 0; u < 8; ++u) {
        int tt = tid + u*256, row = tt>>3, q = tt&7;
        pf[u] = *((const uint4*)(g_cbh + (size_t)(cp*256+row)*CD + kc*64) + q);
    }
}

__global__ void __launch_bounds__(256,1) k_score(){
    extern __shared__ char smraw[];
    __half* Ss = (__half*)smraw;
    __nv_bfloat16* As = (__nv_bfloat16*)(smraw + AS_OFF);
    __nv_bfloat16* Bs = (__nv_bfloat16*)(smraw + BS_OFF);
    unsigned* RM = (unsigned*)(smraw + RM_OFF);
    int tid = threadIdx.x, w = tid>>5, lane = tid&31;
    int grp = lane>>2, tig = lane&3;
    int lr = lane&7, lm = lane>>3;
    int r0 = blockIdx.x*64;
    if (tid < 64) {
        float4 p = *(const float4*)&g_znpart[(size_t)(r0+tid)*4];
        g_znorm[r0+tid] = ((p.x + p.y) + p.z) + p.w;
        RM[tid] = 0u;
    }
    for (int t = tid; t < 2048; t += 256) {
        int row = t>>5, q = t&31;
        *(uint4*)(As + row*AS_STRIDE + q*8) = *((const uint4*)(g_zh + (size_t)(r0+row)*CD) + q);
    }
    uint32_t As_sm = cvta_s(As), Bs_sm = cvta_s(Bs);
    uint32_t aBase = As_sm + (uint32_t)((((lm&1)*8 + lr)*AS_STRIDE + (lm>>1)*8)*2);
    uint32_t bBase = Bs_sm + (uint32_t)(((w*32 + (lm>>1)*8 + lr)*BS_STRIDE + (lm&1)*8)*2);
    unsigned lmax[8];
    #pragma unroll
    for (int i = 0; i < 8; ++i) lmax[i] = 0u;
    uint4 pf[8];
    fetchB(pf, tid, 0, 0);

    for (int cp = 0; cp < 4; ++cp) {
        float acc[4][4][4];
        #pragma unroll
        for (int i = 0; i < 4; ++i)
            #pragma unroll
            for (int j = 0; j < 4; ++j)
                #pragma unroll
                for (int q = 0; q < 4; ++q) acc[i][j][q] = 0.f;
        for (int kc = 0; kc < 4; ++kc) {
            __syncthreads();
            #pragma unroll
            for (int u = 0; u < 8; ++u) {
                int tt = tid + u*256, row = tt>>3, q = tt&7;
                *(uint4*)(Bs + row*BS_STRIDE + q*8) = pf[u];
            }
            int ch = cp*4 + kc + 1;
            if (ch < 16) fetchB(pf, tid, ch>>2, ch&3);
            __syncthreads();
            #pragma unroll
            for (int k16 = 0; k16 < 4; ++k16) {
                uint32_t a[4][4], bp[2][4];
                #pragma unroll
                for (int i = 0; i < 4; ++i)
                    LDM_X4(a[i][0], a[i][1], a[i][2], a[i][3],
                           aBase + (uint32_t)((i*16*AS_STRIDE + kc*64 + k16*16)*2));
                #pragma unroll
                for (int jp = 0; jp < 2; ++jp)
                    LDM_X4(bp[jp][0], bp[jp][1], bp[jp][2], bp[jp][3],
                           bBase + (uint32_t)((jp*16*BS_STRIDE + k16*16)*2));
                #pragma unroll
                for (int i = 0; i < 4; ++i)
                    #pragma unroll
                    for (int j = 0; j < 4; ++j)
                        asm volatile(
                            "mma.sync.aligned.m16n8k16.row.col.f32.bf16.bf16.f32 "
                            "{%0,%1,%2,%3}, {%4,%5,%6,%7}, {%8,%9}, {%0,%1,%2,%3};"
                            : "+f"(acc[i][j][0]), "+f"(acc[i][j][1]),
                              "+f"(acc[i][j][2]), "+f"(acc[i][j][3])
                            : "r"(a[i][0]), "r"(a[i][1]), "r"(a[i][2]), "r"(a[i][3]),
                              "r"(bp[j>>1][(j&1)*2]), "r"(bp[j>>1][(j&1)*2+1]));
            }
        }
        #pragma unroll
        for (int i = 0; i < 4; ++i)
            #pragma unroll
            for (int j = 0; j < 4; ++j) {
                int c_lo = cp*256 + w*32 + j*8 + tig*2;
                float cn0 = 0.5f*g_cnorm[c_lo], cn1 = 0.5f*g_cnorm[c_lo+1];
                float s00 = acc[i][j][0] - cn0, s01 = acc[i][j][1] - cn1;
                float s10 = acc[i][j][2] - cn0, s11 = acc[i][j][3] - cn1;
                int rlo = i*16+grp, rhi = rlo+8;
                *(uint32_t*)(Ss + rlo*SS_STRIDE + c_lo) = h2pack(s00, s01);
                *(uint32_t*)(Ss + rhi*SS_STRIDE + c_lo) = h2pack(s10, s11);
                lmax[i*2]   = max(lmax[i*2],   encf(fmaxf(s00, s01)));
                lmax[i*2+1] = max(lmax[i*2+1], encf(fmaxf(s10, s11)));
            }
    }
    #pragma unroll
    for (int i = 0; i < 4; ++i) {
        atomicMax(&RM[i*16+grp],   lmax[i*2]);
        atomicMax(&RM[i*16+8+grp], lmax[i*2+1]);
    }
    __syncthreads();
    int row = tid>>2, cbase = (tid&3)*256;
    float thr = decf(RM[row]) - TAU;
    const uint4* sp = (const uint4*)(Ss + row*SS_STRIDE + cbase);
    int cnt = 0;
    for (int it = 0; it < 32; ++it) {
        uint4 v = sp[it];
        uint32_t ws[4] = {v.x, v.y, v.z, v.w};
        #pragma unroll
        for (int h = 0; h < 4; ++h) {
            float2 f = __half22float2(*reinterpret_cast<const __half2*>(&ws[h]));
            if (f.x >= thr) ++cnt;
            if (f.y >= thr) ++cnt;
        }
    }
    int incl = cnt;
    #pragma unroll
    for (int o = 1; o < 32; o <<= 1) {
        int t2 = __shfl_up_sync(0xffffffffu, incl, o);
        if (lane >= o) incl += t2;
    }
    int total = __shfl_sync(0xffffffffu, incl, 31);
    int base = 0;
    if (lane == 31 && total) base = atomicAdd(&g_ncand, total);
    base = __shfl_sync(0xffffffffu, base, 31);
    int pos = base + incl - cnt;
    if (total) {
        for (int it = 0; it < 32; ++it) {
            uint4 v = sp[it];
            uint32_t ws[4] = {v.x, v.y, v.z, v.w};
            #pragma unroll
            for (int h = 0; h < 4; ++h) {
                int c = cbase + it*8 + h*2;
                float2 f = __half22float2(*reinterpret_cast<const __half2*>(&ws[h]));
                if (f.x >= thr) {
                    if (pos < CAND_CAP) g_cand[pos] = ((unsigned)(r0+row)<<10) | c;
                    ++pos;
                }
                if (f.y >= thr) {
                    if (pos < CAND_CAP) g_cand[pos] = ((unsigned)(r0+row)<<10) | (c+1);
                    ++pos;
                }
            }
        }
    }
}

__global__ void k_pick2(const float* __restrict__ cb){
    int total = g_ncand; if (total > CAND_CAP) total = CAND_CAP;
    for (int i = blockIdx.x*blockDim.x + threadIdx.x; i < total; i += gridDim.x*blockDim.x) {
        unsigned e = g_cand[i];
        int n = (int)(e>>10), code = (int)(e & 1023u);
        const float4* zp = (const float4*)(g_z + (size_t)n*CD);
        const float4* cp = (const float4*)(cb + (size_t)code*CD);
        float m = 0.f;
        #pragma unroll 8
        for (int q = 0; q < 64; ++q) {
            float4 a = zp[q], b = cp[q];
            m = __fmaf_rn(a.x,b.x,m); m = __fmaf_rn(a.y,b.y,m);
            m = __fmaf_rn(a.z,b.z,m); m = __fmaf_rn(a.w,b.w,m);
        }
        float t = __fadd_rn(g_znorm[n], -__fadd_rn(m,m));
        float d = __fadd_rn(t, g_cnorm[code]);
        unsigned long long key = ((unsigned long long)__float_as_uint(d)<<32) | (unsigned)code;
        atomicMin(&g_key[n], key);
    }
}

__global__ void k_pick3(float* __restrict__ idx_out){
    __shared__ float sm[256];
    int t = threadIdx.x, n = blockIdx.x*256 + t;
    unsigned long long k = g_key[n];
    int bi = (int)(k & 0xffffffffu);
    g_idx[n] = bi;
    float* op = idx_out ? idx_out : g_idxf_dummy;
    op[n] = (float)bi;
    sm[t] = __uint_as_float((unsigned)(k>>32));
    __syncthreads();
    for (int s = 128; s; s >>= 1) { if (t < s) sm[t] += sm[t+s]; __syncthreads(); }
    if (!t) g_part[blockIdx.x] = sm[0];
}

__global__ void k_decode(const float* __restrict__ dec_b, float* __restrict__ out){
    int t = blockIdx.x*256 + threadIdx.x;
    int v = t<<2;
    int j = (v>>2)&63, y = (v>>8)&255, bo = v>>16;
    int b = bo/3, o = bo - b*3, i = y>>2, ki = y&3;
    int n = (b<<12) + (i<<6) + j;
    int id = g_idx[n];
    float4 w = *(const float4*)&g_cb3[id*PATCH + o*16 + (ki<<2)];
    float bb = dec_b[o];
    ((float4*)out)[t] = make_float4(w.x+bb, w.y+bb, w.z+bb, w.w+bb);
}

__global__ void k_loss2(float* __restrict__ lo){
    __shared__ float sm[256]; int t = threadIdx.x;
    sm[t] = g_part[t]; __syncthreads();
    for (int s = 128; s; s >>= 1) { if (t < s) sm[t] += sm[t+s]; __syncthreads(); }
    if (!t) *lo = 1.25f * sm[0] / 16777216.0f;
}

extern "C" void kernel_launch(void* const* d_in, const int* in_sizes, int n_in,
                              void* d_out, int out_size){
    const float* x     = (const float*)d_in[0];
    const float* enc_w = (const float*)d_in[1];
    const float* enc_b = (const float*)d_in[2];
    const float* w1    = (const float*)d_in[3];
    const float* b1    = (const float*)d_in[4];
    const float* cb    = (const float*)d_in[5];
    const float* w2    = (const float*)d_in[6];
    const float* b2    = (const float*)d_in[7];
    const float* dw    = (const float*)d_in[8];
    const float* db    = (const float*)d_in[9];
    float* out = (float*)d_out;

    static bool attr_done = false;
    if (!attr_done) {
        cudaFuncSetAttribute(k_score, cudaFuncAttributeMaxDynamicSharedMemorySize, SC_SMEM);
        attr_done = true;
    }

    k_prep <<<1333, 256>>>(enc_w, enc_b, w1, b1, cb);
    k_G    <<<49, 256>>>(w2, dw, b2);
    k_cb3  <<<1024, 192>>>(cb);
    k_z    <<<dim3(1024,4), 256>>>(x);
    k_score<<<1024, 256, SC_SMEM>>>();
    k_pick2<<<2048, 128>>>(cb);

    bool has_idx  = out_size >= 3145728 + 65536;
    bool has_loss = out_size >= 3145728 + 65536 + 1;
    k_pick3<<<256, 256>>>(has_idx ? out + 3145728 : nullptr);
    k_decode<<<3072, 256>>>(db, out);
    if (has_loss) k_loss2<<<1, 256>>>(out + 3145728 + 65536);
}